// round 9
// baseline (speedup 1.0000x reference)
#include <cuda_runtime.h>
#include <cuda_bf16.h>
#include <cstdint>

#define BT 8192
#define T1 50
#define T2 100

static __device__ float g_seq1[BT * T1 * 128];
static __device__ uint32_t g_wihf[2 * 16 * 8 * 2 * 4 * 32];   // layer2 Wih frags
static __device__ uint32_t g_whhf[2 * 16 * 4 * 2 * 4 * 32];   // layer2 Whh frags
static __device__ uint32_t g_whh1f[2 * 16 * 4 * 2 * 4 * 32];  // layer1 Whh frags

__device__ __forceinline__ float fsig(float x) {
    return __fdividef(1.f, 1.f + __expf(-x));
}
__device__ __forceinline__ float ftanh_(float x) {
    float e = __expf(-2.f * fabsf(x));
    float r = __fdividef(1.f - e, 1.f + e);
    return copysignf(r, x);
}
__device__ __forceinline__ uint32_t pack_bf2(float v0, float v1) {
    __nv_bfloat162 t = __floats2bfloat162_rn(v0, v1);
    return *(uint32_t*)&t;
}
__device__ __forceinline__ void split_pair(float v0, float v1, uint32_t& hi, uint32_t& lo) {
    __nv_bfloat16 h0 = __float2bfloat16_rn(v0), h1 = __float2bfloat16_rn(v1);
    hi = ((uint32_t)*(uint16_t*)&h1 << 16) | *(uint16_t*)&h0;
    lo = pack_bf2(v0 - __bfloat162float(h0), v1 - __bfloat162float(h1));
}
#define MMA(c, a, b0, b1) \
    asm volatile("mma.sync.aligned.m16n8k16.row.col.f32.bf16.bf16.f32 " \
                 "{%0,%1,%2,%3},{%4,%5,%6,%7},{%8,%9},{%0,%1,%2,%3};" \
                 : "+f"((c)[0]), "+f"((c)[1]), "+f"((c)[2]), "+f"((c)[3]) \
                 : "r"((a)[0]), "r"((a)[1]), "r"((a)[2]), "r"((a)[3]), "r"(b0), "r"(b1))

// ===========================================================================
// k_prep: pre-split weights into A-fragment layout (grid-stride, 64 blocks)
// frag (r, lane): row = w*16 + (lane>>2) + (r&1)*8, col = ks*16 + ((r>>1)&1)*8 + (lane&3)*2
// ===========================================================================
__global__ void k_prep(const float* __restrict__ wf, const float* __restrict__ wb,
                       const float* __restrict__ hf, const float* __restrict__ hb,
                       const float* __restrict__ h1f, const float* __restrict__ h1b)
{
    const int gt = blockIdx.x * blockDim.x + threadIdx.x;
    const int nt = gridDim.x * blockDim.x;
    for (int e = gt; e < 2 * 16 * 8 * 4 * 32; e += nt) {
        int l = e & 31, r = (e >> 5) & 3, ks = (e >> 7) & 7, w = (e >> 10) & 15, d = e >> 14;
        const float* W = d ? wb : wf;
        int row = w * 16 + (l >> 2) + (r & 1) * 8;
        int col = ks * 16 + ((r >> 1) & 1) * 8 + (l & 3) * 2;
        uint32_t hi, lo;
        split_pair(W[row * 128 + col], W[row * 128 + col + 1], hi, lo);
        uint32_t base = (((d * 16 + w) * 8 + ks) * 2) * 128 + r * 32 + l;
        g_wihf[base] = hi; g_wihf[base + 128] = lo;
    }
    for (int e = gt; e < 2 * 16 * 4 * 4 * 32; e += nt) {
        int l = e & 31, r = (e >> 5) & 3, ks = (e >> 7) & 3, w = (e >> 9) & 15, d = e >> 13;
        int row = w * 16 + (l >> 2) + (r & 1) * 8;
        int col = ks * 16 + ((r >> 1) & 1) * 8 + (l & 3) * 2;
        uint32_t base = (((d * 16 + w) * 4 + ks) * 2) * 128 + r * 32 + l;
        uint32_t hi, lo;
        const float* W2 = d ? hb : hf;
        split_pair(W2[row * 64 + col], W2[row * 64 + col + 1], hi, lo);
        g_whhf[base] = hi; g_whhf[base + 128] = lo;
        const float* W1 = d ? h1b : h1f;
        split_pair(W1[row * 64 + col], W1[row * 64 + col + 1], hi, lo);
        g_whh1f[base] = hi; g_whh1f[base + 128] = lo;
    }
}

// ===========================================================================
// k_layer1: fc1 + BiLSTM layer 1 on mma.sync -> g_seq1
// CTA = 64 samples, 16 warps; warp w = gates [w*16, w*16+16).
// Input projection is rank-1 (input dim 1): folded into C-fragment init.
// ===========================================================================
#define L1_H1  0                     // h1buf [64][52] fp32   = 13312B
#define L1_HTH 13312                 // hT hi [64][36] words  =  9216B
#define L1_HTL 22528                 // hT lo                 =  9216B
#define L1_GA  31744                 // gact [64][260] fp32   = 66560B
#define L1_SM  98304

__global__ __launch_bounds__(512, 1)
void k_layer1(const float* __restrict__ x,
              const float* __restrict__ fc1_w, const float* __restrict__ fc1_b,
              const float* __restrict__ wih_f, const float* __restrict__ b_f,
              const float* __restrict__ wih_b, const float* __restrict__ b_b)
{
    extern __shared__ char smc[];
    float*    h1  = (float*)(smc + L1_H1);
    uint32_t* hth = (uint32_t*)(smc + L1_HTH);
    uint32_t* htl = (uint32_t*)(smc + L1_HTL);
    float*    ga  = (float*)(smc + L1_GA);

    const int tid = threadIdx.x;
    const int w   = tid >> 5, lid = tid & 31;
    const int grp = lid >> 2, tk = lid & 3;
    const int j = tid & 63, q = tid >> 6;
    const int blk = blockIdx.x;

    // fc1: h1[s][t] = x[s] . fc1_w[t] + fc1_b[t]
    for (int idx = tid; idx < 64 * T1; idx += 512) {
        int s = idx / T1, t = idx - s * T1;
        const float* xr = x + (size_t)(blk * 64 + s) * 20;
        const float* wr = fc1_w + t * 20;
        float acc = __ldg(&fc1_b[t]);
        #pragma unroll
        for (int i = 0; i < 20; i++) acc = fmaf(__ldg(xr + i), __ldg(wr + i), acc);
        h1[s * 52 + t] = acc;
    }

    for (int d = 0; d < 2; d++) {
        const float* bg  = d ? b_b : b_f;
        const float* wih = d ? wih_b : wih_f;
        const float bv0 = __ldg(&bg[w * 16 + grp]);
        const float bv1 = __ldg(&bg[w * 16 + grp + 8]);
        const float wi0 = __ldg(&wih[w * 16 + grp]);
        const float wi1 = __ldg(&wih[w * 16 + grp + 8]);

        // resident Whh A-fragments
        uint32_t wa[32];
        {
            const uint32_t* hp = g_whh1f + (d * 16 + w) * 4 * 256 + lid;
            #pragma unroll
            for (int ks = 0; ks < 4; ks++)
                #pragma unroll
                for (int tm = 0; tm < 2; tm++)
                    #pragma unroll
                    for (int r = 0; r < 4; r++)
                        wa[(ks * 2 + tm) * 4 + r] = __ldg(hp + (ks * 2 + tm) * 128 + r * 32);
        }

        __syncthreads();
        for (int p = tid; p < 4608; p += 512) hth[p] = 0u;   // hth+htl contiguous
        float c8[8];
        #pragma unroll
        for (int i = 0; i < 8; i++) c8[i] = 0.f;
        __syncthreads();

        for (int tt = 0; tt < T1; tt++) {
            const int t = d ? (T1 - 1 - tt) : tt;

            // C init = bias + wih * h1 (rank-1 input projection)
            float cc[8][4];
            #pragma unroll
            for (int n = 0; n < 8; n++) {
                int s0 = n * 8 + 2 * tk;
                float xa = h1[s0 * 52 + t], xb = h1[(s0 + 1) * 52 + t];
                cc[n][0] = fmaf(wi0, xa, bv0);
                cc[n][1] = fmaf(wi0, xb, bv0);
                cc[n][2] = fmaf(wi1, xa, bv1);
                cc[n][3] = fmaf(wi1, xb, bv1);
            }

            // recurrence: cc += Whh @ h  (3-term bf16, A resident)
            #pragma unroll
            for (int ks = 0; ks < 4; ks++) {
                #pragma unroll
                for (int n = 0; n < 8; n++) {
                    int wd = (n * 8 + grp) * 36 + ks * 8 + tk;
                    uint32_t bh0 = hth[wd], bh1 = hth[wd + 4];
                    uint32_t bl0 = htl[wd], bl1 = htl[wd + 4];
                    MMA(cc[n], &wa[(ks * 2 + 0) * 4], bh0, bh1);
                    MMA(cc[n], &wa[(ks * 2 + 0) * 4], bl0, bl1);
                    MMA(cc[n], &wa[(ks * 2 + 1) * 4], bh0, bh1);
                }
            }

            // scatter gates to gact[sample][gate]
            #pragma unroll
            for (int n = 0; n < 8; n++) {
                int s0 = n * 8 + 2 * tk, gcol = w * 16 + grp;
                ga[s0 * 260 + gcol]           = cc[n][0];
                ga[(s0 + 1) * 260 + gcol]     = cc[n][1];
                ga[s0 * 260 + gcol + 8]       = cc[n][2];
                ga[(s0 + 1) * 260 + gcol + 8] = cc[n][3];
            }
            __syncthreads();

            // state update: thread (j,q) -> samples s = q + 8*si
            #pragma unroll
            for (int si = 0; si < 8; si++) {
                const int s = q + si * 8;
                float gi = ga[s * 260 + j],       gf = ga[s * 260 + 64 + j];
                float gg = ga[s * 260 + 128 + j], go = ga[s * 260 + 192 + j];
                float c = fmaf(fsig(gf), c8[si], fsig(gi) * ftanh_(gg));
                c8[si] = c;
                float h = fsig(go) * ftanh_(c);
                g_seq1[((size_t)(blk * 64 + s) * T1 + t) * 128 + d * 64 + j] = h;
                __nv_bfloat16 hh = __float2bfloat16_rn(h);
                __nv_bfloat16 hl = __float2bfloat16_rn(h - __bfloat162float(hh));
                ((__nv_bfloat16*)hth)[s * 72 + j] = hh;
                ((__nv_bfloat16*)htl)[s * 72 + j] = hl;
            }
            __syncthreads();
        }
    }
}

// ===========================================================================
// k_layer2: BiLSTM layer 2 on mma.sync (bf16 hi/lo 3-term) + fc2 + tanh
// (unchanged from round 8 — validated)
// ===========================================================================
#define XT_HI 0
#define XT_LO 17408
#define HT_HI 34816
#define HT_LO 44032
#define GACTO 53248
#define HBUFO 119808
#define OUTAO 137216
#define L2_SM 162816

__global__ __launch_bounds__(512, 1)
void k_layer2(const float* __restrict__ b2_f, const float* __restrict__ b2_b,
              const float* __restrict__ fc2_w, const float* __restrict__ fc2_b,
              float* __restrict__ out)
{
    extern __shared__ char smc[];
    uint32_t* xth = (uint32_t*)(smc + XT_HI);
    uint32_t* xtl = (uint32_t*)(smc + XT_LO);
    uint32_t* hth = (uint32_t*)(smc + HT_HI);
    uint32_t* htl = (uint32_t*)(smc + HT_LO);
    float*    ga  = (float*)(smc + GACTO);
    float*    hbf = (float*)(smc + HBUFO);
    float*    oa  = (float*)(smc + OUTAO);

    const int tid = threadIdx.x;
    const int w   = tid >> 5, lid = tid & 31;
    const int grp = lid >> 2, tk = lid & 3;
    const int j = tid & 63, q = tid >> 6;
    const int blk = blockIdx.x;
    const float fc2bv = __ldg(fc2_b);

    for (int d = 0; d < 2; d++) {
        const float* bg = d ? b2_b : b2_f;
        const float bv0 = __ldg(&bg[w * 16 + grp]);
        const float bv1 = __ldg(&bg[w * 16 + grp + 8]);
        const float fwa = __ldg(&fc2_w[d * 64 + lid]);
        const float fwb = __ldg(&fc2_w[d * 64 + 32 + lid]);

        uint32_t wa[32];
        {
            const uint32_t* hp = g_whhf + (d * 16 + w) * 4 * 256 + lid;
            #pragma unroll
            for (int ks = 0; ks < 4; ks++)
                #pragma unroll
                for (int tm = 0; tm < 2; tm++)
                    #pragma unroll
                    for (int r = 0; r < 4; r++)
                        wa[(ks * 2 + tm) * 4 + r] = __ldg(hp + (ks * 2 + tm) * 128 + r * 32);
        }

        __syncthreads();
        for (int p = tid; p < 4608; p += 512) hth[p] = 0u;
        float c8[8];
        #pragma unroll
        for (int i = 0; i < 8; i++) c8[i] = 0.f;
        float xg[32], cc[8][4];
        __syncthreads();

        for (int tt = 0; tt < T2; tt++) {
            const int t = d ? (T2 - 1 - tt) : tt;

            if ((tt & 1) == 0) {
                const int m = t >> 1;
                {
                    int s = tid >> 3, f0 = (tid & 7) * 16;
                    const float4* xr = (const float4*)(g_seq1 +
                        ((size_t)(blk * 64 + s) * T1 + m) * 128 + f0);
                    int wbase = s * 68 + (f0 >> 1);
                    #pragma unroll
                    for (int i = 0; i < 4; i++) {
                        float4 v = __ldg(xr + i);
                        uint32_t h0, l0, h1, l1;
                        split_pair(v.x, v.y, h0, l0);
                        split_pair(v.z, v.w, h1, l1);
                        xth[wbase + i * 2] = h0; xth[wbase + i * 2 + 1] = h1;
                        xtl[wbase + i * 2] = l0; xtl[wbase + i * 2 + 1] = l1;
                    }
                }
                __syncthreads();
                #pragma unroll
                for (int n = 0; n < 8; n++) {
                    cc[n][0] = bv0; cc[n][1] = bv0; cc[n][2] = bv1; cc[n][3] = bv1;
                }
                const uint32_t* wp = g_wihf + (d * 16 + w) * 8 * 256 + lid;
                for (int ks = 0; ks < 8; ks++) {
                    uint32_t ah[4], al[4];
                    #pragma unroll
                    for (int r = 0; r < 4; r++) {
                        ah[r] = __ldg(wp + ks * 256 + r * 32);
                        al[r] = __ldg(wp + ks * 256 + 128 + r * 32);
                    }
                    #pragma unroll
                    for (int n = 0; n < 8; n++) {
                        int wd = (n * 8 + grp) * 68 + ks * 8 + tk;
                        uint32_t bh0 = xth[wd], bh1 = xth[wd + 4];
                        uint32_t bl0 = xtl[wd], bl1 = xtl[wd + 4];
                        MMA(cc[n], ah, bh0, bh1);
                        MMA(cc[n], ah, bl0, bl1);
                        MMA(cc[n], al, bh0, bh1);
                    }
                }
                #pragma unroll
                for (int n = 0; n < 8; n++)
                    #pragma unroll
                    for (int r = 0; r < 4; r++) xg[n * 4 + r] = cc[n][r];
            } else {
                #pragma unroll
                for (int n = 0; n < 8; n++)
                    #pragma unroll
                    for (int r = 0; r < 4; r++) cc[n][r] = xg[n * 4 + r];
            }

            #pragma unroll
            for (int ks = 0; ks < 4; ks++) {
                #pragma unroll
                for (int n = 0; n < 8; n++) {
                    int wd = (n * 8 + grp) * 36 + ks * 8 + tk;
                    uint32_t bh0 = hth[wd], bh1 = hth[wd + 4];
                    uint32_t bl0 = htl[wd], bl1 = htl[wd + 4];
                    MMA(cc[n], &wa[(ks * 2 + 0) * 4], bh0, bh1);
                    MMA(cc[n], &wa[(ks * 2 + 0) * 4], bl0, bl1);
                    MMA(cc[n], &wa[(ks * 2 + 1) * 4], bh0, bh1);
                }
            }

            #pragma unroll
            for (int n = 0; n < 8; n++) {
                int s0 = n * 8 + 2 * tk, gcol = w * 16 + grp;
                ga[s0 * 260 + gcol]           = cc[n][0];
                ga[(s0 + 1) * 260 + gcol]     = cc[n][1];
                ga[s0 * 260 + gcol + 8]       = cc[n][2];
                ga[(s0 + 1) * 260 + gcol + 8] = cc[n][3];
            }
            __syncthreads();

            #pragma unroll
            for (int si = 0; si < 8; si++) {
                const int s = q + si * 8;
                float gi = ga[s * 260 + j],       gf = ga[s * 260 + 64 + j];
                float gg = ga[s * 260 + 128 + j], go = ga[s * 260 + 192 + j];
                float c = fmaf(fsig(gf), c8[si], fsig(gi) * ftanh_(gg));
                c8[si] = c;
                float h = fsig(go) * ftanh_(c);
                hbf[s * 68 + j] = h;
                __nv_bfloat16 hh = __float2bfloat16_rn(h);
                __nv_bfloat16 hl = __float2bfloat16_rn(h - __bfloat162float(hh));
                ((__nv_bfloat16*)hth)[s * 72 + j] = hh;
                ((__nv_bfloat16*)htl)[s * 72 + j] = hl;
            }
            __syncthreads();

            #pragma unroll
            for (int si2 = 0; si2 < 4; si2++) {
                const int s = w * 4 + si2;
                float pm = hbf[s * 68 + lid] * fwa + hbf[s * 68 + 32 + lid] * fwb;
                #pragma unroll
                for (int o = 16; o > 0; o >>= 1)
                    pm += __shfl_down_sync(0xffffffffu, pm, o);
                if (lid == 0) {
                    if (d == 0) oa[s * 100 + t] = pm;
                    else out[(size_t)(blk * 64 + s) * T2 + t] = ftanh_(oa[s * 100 + t] + pm + fc2bv);
                }
            }
        }
    }
}

// ---------------------------------------------------------------------------
extern "C" void kernel_launch(void* const* d_in, const int* in_sizes, int n_in,
                              void* d_out, int out_size)
{
    const float* x    = (const float*)d_in[0];
    const float* fc1w = (const float*)d_in[1];
    const float* fc1b = (const float*)d_in[2];
    const float* r1wf = (const float*)d_in[3];
    const float* r1hf = (const float*)d_in[4];
    const float* r1bf = (const float*)d_in[5];
    const float* r1wb = (const float*)d_in[6];
    const float* r1hb = (const float*)d_in[7];
    const float* r1bb = (const float*)d_in[8];
    const float* r2wf = (const float*)d_in[9];
    const float* r2hf = (const float*)d_in[10];
    const float* r2bf = (const float*)d_in[11];
    const float* r2wb = (const float*)d_in[12];
    const float* r2hb = (const float*)d_in[13];
    const float* r2bb = (const float*)d_in[14];
    const float* fc2w = (const float*)d_in[15];
    const float* fc2b = (const float*)d_in[16];
    float* out = (float*)d_out;

    cudaFuncSetAttribute(k_layer1, cudaFuncAttributeMaxDynamicSharedMemorySize, L1_SM);
    cudaFuncSetAttribute(k_layer2, cudaFuncAttributeMaxDynamicSharedMemorySize, L2_SM);

    k_prep<<<64, 256>>>(r2wf, r2wb, r2hf, r2hb, r1hf, r1hb);
    k_layer1<<<128, 512, L1_SM>>>(x, fc1w, fc1b, r1wf, r1bf, r1wb, r1bb);
    k_layer2<<<128, 512, L2_SM>>>(r2bf, r2bb, fc2w, fc2b, out);
}

// round 10
// speedup vs baseline: 1.0516x; 1.0516x over previous
#include <cuda_runtime.h>
#include <cuda_bf16.h>
#include <cstdint>

#define BT 8192
#define T1 50
#define T2 100
#define G1 32
#define HB_P 68
#define GA_P 260

static __device__ float g_seq1[BT * T1 * 128];
static __device__ uint32_t g_wihf[2 * 16 * 8 * 2 * 4 * 32];   // layer2 Wih frags
static __device__ uint32_t g_whhf[2 * 16 * 4 * 2 * 4 * 32];   // layer2 Whh frags
static __device__ float g_xg[2 * 128 * 50 * 16 * 1024];       // proj results (839MB)

__device__ __forceinline__ float fsig(float x) {
    return __fdividef(1.f, 1.f + __expf(-x));
}
__device__ __forceinline__ float ftanh_(float x) {
    float e = __expf(-2.f * fabsf(x));
    float r = __fdividef(1.f - e, 1.f + e);
    return copysignf(r, x);
}
__device__ __forceinline__ float dot4acc(float4 w, float4 h, float a) {
    a = fmaf(w.x, h.x, a); a = fmaf(w.y, h.y, a);
    a = fmaf(w.z, h.z, a); return fmaf(w.w, h.w, a);
}
__device__ __forceinline__ uint32_t pack_bf2(float v0, float v1) {
    __nv_bfloat162 t = __floats2bfloat162_rn(v0, v1);
    return *(uint32_t*)&t;
}
__device__ __forceinline__ void split_pair(float v0, float v1, uint32_t& hi, uint32_t& lo) {
    __nv_bfloat16 h0 = __float2bfloat16_rn(v0), h1 = __float2bfloat16_rn(v1);
    hi = ((uint32_t)*(uint16_t*)&h1 << 16) | *(uint16_t*)&h0;
    lo = pack_bf2(v0 - __bfloat162float(h0), v1 - __bfloat162float(h1));
}
#define MMA(c, a, b0, b1) \
    asm volatile("mma.sync.aligned.m16n8k16.row.col.f32.bf16.bf16.f32 " \
                 "{%0,%1,%2,%3},{%4,%5,%6,%7},{%8,%9},{%0,%1,%2,%3};" \
                 : "+f"((c)[0]), "+f"((c)[1]), "+f"((c)[2]), "+f"((c)[3]) \
                 : "r"((a)[0]), "r"((a)[1]), "r"((a)[2]), "r"((a)[3]), "r"(b0), "r"(b1))

// ===========================================================================
// k_prep: pre-split layer2 weights into A-fragment layout (parallel)
// frag (r,lane): row = w*16 + (lane>>2) + (r&1)*8, col = ks*16 + ((r>>1)&1)*8 + (lane&3)*2
// ===========================================================================
__global__ void k_prep(const float* __restrict__ wf, const float* __restrict__ wb,
                       const float* __restrict__ hf, const float* __restrict__ hb)
{
    const int gt = blockIdx.x * blockDim.x + threadIdx.x;
    const int nt = gridDim.x * blockDim.x;
    for (int e = gt; e < 2 * 16 * 8 * 4 * 32; e += nt) {
        int l = e & 31, r = (e >> 5) & 3, ks = (e >> 7) & 7, w = (e >> 10) & 15, d = e >> 14;
        const float* W = d ? wb : wf;
        int row = w * 16 + (l >> 2) + (r & 1) * 8;
        int col = ks * 16 + ((r >> 1) & 1) * 8 + (l & 3) * 2;
        uint32_t hi, lo;
        split_pair(W[row * 128 + col], W[row * 128 + col + 1], hi, lo);
        uint32_t base = (((d * 16 + w) * 8 + ks) * 2) * 128 + r * 32 + l;
        g_wihf[base] = hi; g_wihf[base + 128] = lo;
    }
    for (int e = gt; e < 2 * 16 * 4 * 4 * 32; e += nt) {
        int l = e & 31, r = (e >> 5) & 3, ks = (e >> 7) & 3, w = (e >> 9) & 15, d = e >> 13;
        const float* W = d ? hb : hf;
        int row = w * 16 + (l >> 2) + (r & 1) * 8;
        int col = ks * 16 + ((r >> 1) & 1) * 8 + (l & 3) * 2;
        uint32_t hi, lo;
        split_pair(W[row * 64 + col], W[row * 64 + col + 1], hi, lo);
        uint32_t base = (((d * 16 + w) * 4 + ks) * 2) * 128 + r * 32 + l;
        g_whhf[base] = hi; g_whhf[base + 128] = lo;
    }
}

// ===========================================================================
// k_layer1: fc1 + BiLSTM layer 1 (FFMA, round-8 validated version)
// ===========================================================================
__global__ __launch_bounds__(256, 2)
void k_layer1(const float* __restrict__ x,
              const float* __restrict__ fc1_w, const float* __restrict__ fc1_b,
              const float* __restrict__ wih_f, const float* __restrict__ whh_f, const float* __restrict__ b_f,
              const float* __restrict__ wih_b, const float* __restrict__ whh_b, const float* __restrict__ b_b)
{
    extern __shared__ float sm[];
    float* gact  = sm;
    float* hbuf  = gact + G1 * GA_P;
    float* h1buf = hbuf + G1 * HB_P;

    const int tid  = threadIdx.x;
    const int base = blockIdx.x * G1;
    const int g    = tid;
    const int j    = tid & 63, q = tid >> 6;

    for (int idx = tid; idx < G1 * T1; idx += 256) {
        int s = idx / T1, t = idx - s * T1;
        const float* xr = x + (base + s) * 20;
        const float* wr = fc1_w + t * 20;
        float acc = fc1_b[t];
        #pragma unroll
        for (int i = 0; i < 20; i++) acc = fmaf(xr[i], wr[i], acc);
        h1buf[s * T1 + t] = acc;
    }

    for (int d = 0; d < 2; d++) {
        const float* whh = d ? whh_b : whh_f;
        const float* wih = d ? wih_b : wih_f;
        const float* bg  = d ? b_b   : b_f;

        __syncthreads();
        for (int idx = tid; idx < G1 * HB_P; idx += 256) hbuf[idx] = 0.f;

        float4 wv[16];
        const float4* wgp = (const float4*)(whh + g * 64);
        #pragma unroll
        for (int kc = 0; kc < 16; kc++) wv[kc] = __ldg(wgp + kc);
        const float wihg = __ldg(wih + g);
        const float bsg  = __ldg(bg + g);

        float c_reg[8];
        #pragma unroll
        for (int i = 0; i < 8; i++) c_reg[i] = 0.f;
        __syncthreads();

        const bool tanh_gate = ((g >> 6) == 2);

        for (int tt = 0; tt < T1; tt++) {
            const int t = d ? (T1 - 1 - tt) : tt;
            for (int sg = 0; sg < G1; sg += 2) {
                float a0 = fmaf(h1buf[(sg + 0) * T1 + t], wihg, bsg);
                float a1 = fmaf(h1buf[(sg + 1) * T1 + t], wihg, bsg);
                #pragma unroll
                for (int kc = 0; kc < 16; kc++) {
                    float4 w4 = wv[kc];
                    float4 h0 = *(const float4*)(hbuf + (sg + 0) * HB_P + kc * 4);
                    float4 h1 = *(const float4*)(hbuf + (sg + 1) * HB_P + kc * 4);
                    a0 = dot4acc(w4, h0, a0);
                    a1 = dot4acc(w4, h1, a1);
                }
                gact[(sg + 0) * GA_P + g] = tanh_gate ? ftanh_(a0) : fsig(a0);
                gact[(sg + 1) * GA_P + g] = tanh_gate ? ftanh_(a1) : fsig(a1);
            }
            __syncthreads();
            #pragma unroll
            for (int si = 0; si < 8; si++) {
                const int s = q + si * 4;
                float gi = gact[s * GA_P + j];
                float gf = gact[s * GA_P + 64 + j];
                float gg = gact[s * GA_P + 128 + j];
                float go = gact[s * GA_P + 192 + j];
                float c  = fmaf(gf, c_reg[si], gi * gg);
                c_reg[si] = c;
                float h = go * ftanh_(c);
                hbuf[s * HB_P + j] = h;
                g_seq1[((base + s) * T1 + t) * 128 + d * 64 + j] = h;
            }
            __syncthreads();
        }
    }
}

// ===========================================================================
// k_proj: all layer2 input projections (bf16 hi/lo 3-term mma) -> g_xg
// CTA = (d, blk of 64 samples); xg layout: warp-interleaved for coalesced l2 reads
// ===========================================================================
#define PJ_XH 0
#define PJ_XL 17408
#define PJ_SM 34816

__global__ __launch_bounds__(512, 1)
void k_proj(const float* __restrict__ b2_f, const float* __restrict__ b2_b)
{
    extern __shared__ char smc[];
    uint32_t* xth = (uint32_t*)(smc + PJ_XH);
    uint32_t* xtl = (uint32_t*)(smc + PJ_XL);

    const int tid = threadIdx.x;
    const int w   = tid >> 5, lid = tid & 31;
    const int grp = lid >> 2, tk = lid & 3;
    const int d   = blockIdx.x >> 7, blk = blockIdx.x & 127;

    const float* bg = d ? b2_b : b2_f;
    const float bv0 = __ldg(&bg[w * 16 + grp]);
    const float bv1 = __ldg(&bg[w * 16 + grp + 8]);

    for (int m = 0; m < T1; m++) {
        {   // stage x chunk [64][128] -> bf16 hi/lo (rows of 68 words)
            int s = tid >> 3, f0 = (tid & 7) * 16;
            const float4* xr = (const float4*)(g_seq1 +
                ((size_t)(blk * 64 + s) * T1 + m) * 128 + f0);
            int wbase = s * 68 + (f0 >> 1);
            #pragma unroll
            for (int i = 0; i < 4; i++) {
                float4 v = __ldg(xr + i);
                uint32_t h0, l0, h1, l1;
                split_pair(v.x, v.y, h0, l0);
                split_pair(v.z, v.w, h1, l1);
                xth[wbase + i * 2] = h0; xth[wbase + i * 2 + 1] = h1;
                xtl[wbase + i * 2] = l0; xtl[wbase + i * 2 + 1] = l1;
            }
        }
        __syncthreads();

        float cc[8][4];
        #pragma unroll
        for (int n = 0; n < 8; n++) {
            cc[n][0] = bv0; cc[n][1] = bv0; cc[n][2] = bv1; cc[n][3] = bv1;
        }
        const uint32_t* wp = g_wihf + (d * 16 + w) * 8 * 256 + lid;
        for (int ks = 0; ks < 8; ks++) {
            uint32_t ah[4], al[4];
            #pragma unroll
            for (int r = 0; r < 4; r++) {
                ah[r] = __ldg(wp + ks * 256 + r * 32);
                al[r] = __ldg(wp + ks * 256 + 128 + r * 32);
            }
            #pragma unroll
            for (int n = 0; n < 8; n++) {
                int wd = (n * 8 + grp) * 68 + ks * 8 + tk;
                uint32_t bh0 = xth[wd], bh1 = xth[wd + 4];
                uint32_t bl0 = xtl[wd], bl1 = xtl[wd + 4];
                MMA(cc[n], ah, bh0, bh1);
                MMA(cc[n], ah, bl0, bl1);
                MMA(cc[n], al, bh0, bh1);
            }
        }
        // store: warp block of 1024 floats; value-group n at n*128 + lane*4
        float* op = g_xg + ((((size_t)(d * 128 + blk) * 50 + m) * 16 + w) * 8) * 128 + lid * 4;
        #pragma unroll
        for (int n = 0; n < 8; n++) {
            float4 v;
            v.x = cc[n][0]; v.y = cc[n][1]; v.z = cc[n][2]; v.w = cc[n][3];
            *(float4*)(op + n * 128) = v;
        }
        __syncthreads();
    }
}

// ===========================================================================
// k_layer2: BiLSTM layer 2 recurrence (mma) + fc2 + tanh; xg from g_xg
// ===========================================================================
#define HT_HI 0
#define HT_LO 9216
#define GACTO 18432
#define HBUFO 84992
#define OUTAO 102400
#define L2_SM 128000

__global__ __launch_bounds__(512, 1)
void k_layer2(const float* __restrict__ fc2_w, const float* __restrict__ fc2_b,
              float* __restrict__ out)
{
    extern __shared__ char smc[];
    uint32_t* hth = (uint32_t*)(smc + HT_HI);
    uint32_t* htl = (uint32_t*)(smc + HT_LO);
    float*    ga  = (float*)(smc + GACTO);
    float*    hbf = (float*)(smc + HBUFO);
    float*    oa  = (float*)(smc + OUTAO);

    const int tid = threadIdx.x;
    const int w   = tid >> 5, lid = tid & 31;
    const int grp = lid >> 2, tk = lid & 3;
    const int j = tid & 63, q = tid >> 6;
    const int blk = blockIdx.x;
    const float fc2bv = __ldg(fc2_b);

    for (int d = 0; d < 2; d++) {
        const float fwa = __ldg(&fc2_w[d * 64 + lid]);
        const float fwb = __ldg(&fc2_w[d * 64 + 32 + lid]);

        // resident Whh A-fragments
        uint32_t wa[32];
        {
            const uint32_t* hp = g_whhf + (d * 16 + w) * 4 * 256 + lid;
            #pragma unroll
            for (int ks = 0; ks < 4; ks++)
                #pragma unroll
                for (int tm = 0; tm < 2; tm++)
                    #pragma unroll
                    for (int r = 0; r < 4; r++)
                        wa[(ks * 2 + tm) * 4 + r] = __ldg(hp + (ks * 2 + tm) * 128 + r * 32);
        }

        __syncthreads();
        for (int p = tid; p < 4608; p += 512) hth[p] = 0u;   // hth+htl contiguous
        float c8[8];
        #pragma unroll
        for (int i = 0; i < 8; i++) c8[i] = 0.f;

        // initial xg prefetch (pair m0)
        float xgv[32];
        {
            const int m0 = d ? 49 : 0;
            const float* xp = g_xg + ((((size_t)(d * 128 + blk) * 50 + m0) * 16 + w) * 8) * 128 + lid * 4;
            #pragma unroll
            for (int n = 0; n < 8; n++) {
                float4 v = __ldg((const float4*)(xp + n * 128));
                xgv[n * 4 + 0] = v.x; xgv[n * 4 + 1] = v.y;
                xgv[n * 4 + 2] = v.z; xgv[n * 4 + 3] = v.w;
            }
        }
        __syncthreads();

        for (int tt = 0; tt < T2; tt++) {
            const int t = d ? (T2 - 1 - tt) : tt;

            // gates init from prefetched projection
            float cc[8][4];
            #pragma unroll
            for (int n = 0; n < 8; n++)
                #pragma unroll
                for (int r = 0; r < 4; r++) cc[n][r] = xgv[n * 4 + r];

            // at odd steps: prefetch next pair's xg (hides under MMA+epilogue)
            if (tt & 1) {
                const int m  = t >> 1;
                const int mn = d ? (m - 1) : (m + 1);
                if (mn >= 0 && mn < 50) {
                    const float* xp = g_xg + ((((size_t)(d * 128 + blk) * 50 + mn) * 16 + w) * 8) * 128 + lid * 4;
                    #pragma unroll
                    for (int n = 0; n < 8; n++) {
                        float4 v = __ldg((const float4*)(xp + n * 128));
                        xgv[n * 4 + 0] = v.x; xgv[n * 4 + 1] = v.y;
                        xgv[n * 4 + 2] = v.z; xgv[n * 4 + 3] = v.w;
                    }
                }
            }

            // recurrence: cc += Whh @ h  (3-term, A resident)
            #pragma unroll
            for (int ks = 0; ks < 4; ks++) {
                #pragma unroll
                for (int n = 0; n < 8; n++) {
                    int wd = (n * 8 + grp) * 36 + ks * 8 + tk;
                    uint32_t bh0 = hth[wd], bh1 = hth[wd + 4];
                    uint32_t bl0 = htl[wd], bl1 = htl[wd + 4];
                    MMA(cc[n], &wa[(ks * 2 + 0) * 4], bh0, bh1);
                    MMA(cc[n], &wa[(ks * 2 + 0) * 4], bl0, bl1);
                    MMA(cc[n], &wa[(ks * 2 + 1) * 4], bh0, bh1);
                }
            }

            // scatter gates
            #pragma unroll
            for (int n = 0; n < 8; n++) {
                int s0 = n * 8 + 2 * tk, gcol = w * 16 + grp;
                ga[s0 * 260 + gcol]           = cc[n][0];
                ga[(s0 + 1) * 260 + gcol]     = cc[n][1];
                ga[s0 * 260 + gcol + 8]       = cc[n][2];
                ga[(s0 + 1) * 260 + gcol + 8] = cc[n][3];
            }
            __syncthreads();

            // state update
            #pragma unroll
            for (int si = 0; si < 8; si++) {
                const int s = q + si * 8;
                float gi = ga[s * 260 + j],       gf = ga[s * 260 + 64 + j];
                float gg = ga[s * 260 + 128 + j], go = ga[s * 260 + 192 + j];
                float c = fmaf(fsig(gf), c8[si], fsig(gi) * ftanh_(gg));
                c8[si] = c;
                float h = fsig(go) * ftanh_(c);
                hbf[s * 68 + j] = h;
                __nv_bfloat16 hh = __float2bfloat16_rn(h);
                __nv_bfloat16 hl = __float2bfloat16_rn(h - __bfloat162float(hh));
                ((__nv_bfloat16*)hth)[s * 72 + j] = hh;
                ((__nv_bfloat16*)htl)[s * 72 + j] = hl;
            }
            __syncthreads();

            // fc2
            #pragma unroll
            for (int si2 = 0; si2 < 4; si2++) {
                const int s = w * 4 + si2;
                float pm = hbf[s * 68 + lid] * fwa + hbf[s * 68 + 32 + lid] * fwb;
                #pragma unroll
                for (int o = 16; o > 0; o >>= 1)
                    pm += __shfl_down_sync(0xffffffffu, pm, o);
                if (lid == 0) {
                    if (d == 0) oa[s * 100 + t] = pm;
                    else out[(size_t)(blk * 64 + s) * T2 + t] = ftanh_(oa[s * 100 + t] + pm + fc2bv);
                }
            }
        }
    }
}

// ---------------------------------------------------------------------------
extern "C" void kernel_launch(void* const* d_in, const int* in_sizes, int n_in,
                              void* d_out, int out_size)
{
    const float* x    = (const float*)d_in[0];
    const float* fc1w = (const float*)d_in[1];
    const float* fc1b = (const float*)d_in[2];
    const float* r1wf = (const float*)d_in[3];
    const float* r1hf = (const float*)d_in[4];
    const float* r1bf = (const float*)d_in[5];
    const float* r1wb = (const float*)d_in[6];
    const float* r1hb = (const float*)d_in[7];
    const float* r1bb = (const float*)d_in[8];
    const float* r2wf = (const float*)d_in[9];
    const float* r2hf = (const float*)d_in[10];
    const float* r2bf = (const float*)d_in[11];
    const float* r2wb = (const float*)d_in[12];
    const float* r2hb = (const float*)d_in[13];
    const float* r2bb = (const float*)d_in[14];
    const float* fc2w = (const float*)d_in[15];
    const float* fc2b = (const float*)d_in[16];
    float* out = (float*)d_out;

    const size_t SM1 = (size_t)(G1 * GA_P + G1 * HB_P + G1 * T1) * sizeof(float);

    cudaFuncSetAttribute(k_layer1, cudaFuncAttributeMaxDynamicSharedMemorySize, (int)SM1);
    cudaFuncSetAttribute(k_proj,   cudaFuncAttributeMaxDynamicSharedMemorySize, PJ_SM);
    cudaFuncSetAttribute(k_layer2, cudaFuncAttributeMaxDynamicSharedMemorySize, L2_SM);

    k_prep<<<64, 256>>>(r2wf, r2wb, r2hf, r2hb);
    k_layer1<<<BT / G1, 256, SM1>>>(x, fc1w, fc1b, r1wf, r1hf, r1bf, r1wb, r1hb, r1bb);
    k_proj<<<256, 512, PJ_SM>>>(r2bf, r2bb);
    k_layer2<<<128, 512, L2_SM>>>(fc2w, fc2b, out);
}

// round 11
// speedup vs baseline: 1.0707x; 1.0181x over previous
#include <cuda_runtime.h>
#include <cuda_bf16.h>
#include <cstdint>

#define BT 8192
#define T1 50
#define T2 100
#define G1 32
#define HB_P 68
#define GA_P 260

static __device__ float g_seq1[BT * T1 * 128];
static __device__ uint32_t g_wihf[2 * 16 * 8 * 2 * 4 * 32];   // layer2 Wih frags
static __device__ uint32_t g_whhf[2 * 16 * 4 * 2 * 4 * 32];   // layer2 Whh frags
static __device__ float g_xg[2 * 128 * 50 * 16 * 1024];       // proj results (839MB)

__device__ __forceinline__ float fsig(float x) {
    return __fdividef(1.f, 1.f + __expf(-x));
}
__device__ __forceinline__ float ftanh_(float x) {
    float e = __expf(-2.f * fabsf(x));
    float r = __fdividef(1.f - e, 1.f + e);
    return copysignf(r, x);
}
__device__ __forceinline__ float dot4acc(float4 w, float4 h, float a) {
    a = fmaf(w.x, h.x, a); a = fmaf(w.y, h.y, a);
    a = fmaf(w.z, h.z, a); return fmaf(w.w, h.w, a);
}
__device__ __forceinline__ uint32_t pack_bf2(float v0, float v1) {
    __nv_bfloat162 t = __floats2bfloat162_rn(v0, v1);
    return *(uint32_t*)&t;
}
__device__ __forceinline__ void split_pair(float v0, float v1, uint32_t& hi, uint32_t& lo) {
    __nv_bfloat16 h0 = __float2bfloat16_rn(v0), h1 = __float2bfloat16_rn(v1);
    hi = ((uint32_t)*(uint16_t*)&h1 << 16) | *(uint16_t*)&h0;
    lo = pack_bf2(v0 - __bfloat162float(h0), v1 - __bfloat162float(h1));
}
#define MMA(c, a, b0, b1) \
    asm volatile("mma.sync.aligned.m16n8k16.row.col.f32.bf16.bf16.f32 " \
                 "{%0,%1,%2,%3},{%4,%5,%6,%7},{%8,%9},{%0,%1,%2,%3};" \
                 : "+f"((c)[0]), "+f"((c)[1]), "+f"((c)[2]), "+f"((c)[3]) \
                 : "r"((a)[0]), "r"((a)[1]), "r"((a)[2]), "r"((a)[3]), "r"(b0), "r"(b1))

// ===========================================================================
// k_prep: pre-split layer2 weights into A-fragment layout (parallel)
// frag (r,lane): row = w*16 + (lane>>2) + (r&1)*8, col = ks*16 + ((r>>1)&1)*8 + (lane&3)*2
// ===========================================================================
__global__ void k_prep(const float* __restrict__ wf, const float* __restrict__ wb,
                       const float* __restrict__ hf, const float* __restrict__ hb)
{
    const int gt = blockIdx.x * blockDim.x + threadIdx.x;
    const int nt = gridDim.x * blockDim.x;
    for (int e = gt; e < 2 * 16 * 8 * 4 * 32; e += nt) {
        int l = e & 31, r = (e >> 5) & 3, ks = (e >> 7) & 7, w = (e >> 10) & 15, d = e >> 14;
        const float* W = d ? wb : wf;
        int row = w * 16 + (l >> 2) + (r & 1) * 8;
        int col = ks * 16 + ((r >> 1) & 1) * 8 + (l & 3) * 2;
        uint32_t hi, lo;
        split_pair(W[row * 128 + col], W[row * 128 + col + 1], hi, lo);
        uint32_t base = (((d * 16 + w) * 8 + ks) * 2) * 128 + r * 32 + l;
        g_wihf[base] = hi; g_wihf[base + 128] = lo;
    }
    for (int e = gt; e < 2 * 16 * 4 * 4 * 32; e += nt) {
        int l = e & 31, r = (e >> 5) & 3, ks = (e >> 7) & 3, w = (e >> 9) & 15, d = e >> 13;
        const float* W = d ? hb : hf;
        int row = w * 16 + (l >> 2) + (r & 1) * 8;
        int col = ks * 16 + ((r >> 1) & 1) * 8 + (l & 3) * 2;
        uint32_t hi, lo;
        split_pair(W[row * 64 + col], W[row * 64 + col + 1], hi, lo);
        uint32_t base = (((d * 16 + w) * 4 + ks) * 2) * 128 + r * 32 + l;
        g_whhf[base] = hi; g_whhf[base + 128] = lo;
    }
}

// ===========================================================================
// k_layer1: fc1 + BiLSTM layer 1 (FFMA, validated)
// ===========================================================================
__global__ __launch_bounds__(256, 2)
void k_layer1(const float* __restrict__ x,
              const float* __restrict__ fc1_w, const float* __restrict__ fc1_b,
              const float* __restrict__ wih_f, const float* __restrict__ whh_f, const float* __restrict__ b_f,
              const float* __restrict__ wih_b, const float* __restrict__ whh_b, const float* __restrict__ b_b)
{
    extern __shared__ float sm[];
    float* gact  = sm;
    float* hbuf  = gact + G1 * GA_P;
    float* h1buf = hbuf + G1 * HB_P;

    const int tid  = threadIdx.x;
    const int base = blockIdx.x * G1;
    const int g    = tid;
    const int j    = tid & 63, q = tid >> 6;

    for (int idx = tid; idx < G1 * T1; idx += 256) {
        int s = idx / T1, t = idx - s * T1;
        const float* xr = x + (base + s) * 20;
        const float* wr = fc1_w + t * 20;
        float acc = fc1_b[t];
        #pragma unroll
        for (int i = 0; i < 20; i++) acc = fmaf(xr[i], wr[i], acc);
        h1buf[s * T1 + t] = acc;
    }

    for (int d = 0; d < 2; d++) {
        const float* whh = d ? whh_b : whh_f;
        const float* wih = d ? wih_b : wih_f;
        const float* bg  = d ? b_b   : b_f;

        __syncthreads();
        for (int idx = tid; idx < G1 * HB_P; idx += 256) hbuf[idx] = 0.f;

        float4 wv[16];
        const float4* wgp = (const float4*)(whh + g * 64);
        #pragma unroll
        for (int kc = 0; kc < 16; kc++) wv[kc] = __ldg(wgp + kc);
        const float wihg = __ldg(wih + g);
        const float bsg  = __ldg(bg + g);

        float c_reg[8];
        #pragma unroll
        for (int i = 0; i < 8; i++) c_reg[i] = 0.f;
        __syncthreads();

        const bool tanh_gate = ((g >> 6) == 2);

        for (int tt = 0; tt < T1; tt++) {
            const int t = d ? (T1 - 1 - tt) : tt;
            for (int sg = 0; sg < G1; sg += 2) {
                float a0 = fmaf(h1buf[(sg + 0) * T1 + t], wihg, bsg);
                float a1 = fmaf(h1buf[(sg + 1) * T1 + t], wihg, bsg);
                #pragma unroll
                for (int kc = 0; kc < 16; kc++) {
                    float4 w4 = wv[kc];
                    float4 h0 = *(const float4*)(hbuf + (sg + 0) * HB_P + kc * 4);
                    float4 h1 = *(const float4*)(hbuf + (sg + 1) * HB_P + kc * 4);
                    a0 = dot4acc(w4, h0, a0);
                    a1 = dot4acc(w4, h1, a1);
                }
                gact[(sg + 0) * GA_P + g] = tanh_gate ? ftanh_(a0) : fsig(a0);
                gact[(sg + 1) * GA_P + g] = tanh_gate ? ftanh_(a1) : fsig(a1);
            }
            __syncthreads();
            #pragma unroll
            for (int si = 0; si < 8; si++) {
                const int s = q + si * 4;
                float gi = gact[s * GA_P + j];
                float gf = gact[s * GA_P + 64 + j];
                float gg = gact[s * GA_P + 128 + j];
                float go = gact[s * GA_P + 192 + j];
                float c  = fmaf(gf, c_reg[si], gi * gg);
                c_reg[si] = c;
                float h = go * ftanh_(c);
                hbuf[s * HB_P + j] = h;
                g_seq1[((base + s) * T1 + t) * 128 + d * 64 + j] = h;
            }
            __syncthreads();
        }
    }
}

// ===========================================================================
// k_proj v2: layer2 input projections -> g_xg
// Weights staged ONCE per CTA into SMEM (conflict-free); m-range split over
// 2 CTAs for wave balance. grid = (d, blk, half) = 512 CTAs x 25 m each.
// ===========================================================================
#define PJ_W  0                         // 128KB weight frags
#define PJ_XH 131072                    // x hi tiles (64 rows x 68 words)
#define PJ_XL (131072 + 17408)
#define PJ_SM (131072 + 34816)

__global__ __launch_bounds__(512, 1)
void k_proj(const float* __restrict__ b2_f, const float* __restrict__ b2_b)
{
    extern __shared__ char smc[];
    uint32_t* wsm = (uint32_t*)(smc + PJ_W);
    uint32_t* xth = (uint32_t*)(smc + PJ_XH);
    uint32_t* xtl = (uint32_t*)(smc + PJ_XL);

    const int tid = threadIdx.x;
    const int w   = tid >> 5, lid = tid & 31;
    const int grp = lid >> 2, tk = lid & 3;
    const int bi  = blockIdx.x;
    const int d   = bi >> 8, blk = (bi >> 1) & 127, half = bi & 1;
    const int m0  = half * 25;

    const float* bg = d ? b2_b : b2_f;
    const float bv0 = __ldg(&bg[w * 16 + grp]);
    const float bv1 = __ldg(&bg[w * 16 + grp + 8]);

    // stage this d's Wih fragments into SMEM once (32768 words = 128KB)
    {
        const uint32_t* src = g_wihf + d * 32768;
        for (int p = tid; p < 32768; p += 512) wsm[p] = __ldg(src + p);
    }
    __syncthreads();
    const uint32_t* wp = wsm + w * 2048 + lid;   // [ks*256 + term*128 + r*32]

    for (int mi = 0; mi < 25; mi++) {
        const int m = m0 + mi;
        {   // stage x chunk [64][128] -> bf16 hi/lo (rows of 68 words)
            int s = tid >> 3, f0 = (tid & 7) * 16;
            const float4* xr = (const float4*)(g_seq1 +
                ((size_t)(blk * 64 + s) * T1 + m) * 128 + f0);
            int wbase = s * 68 + (f0 >> 1);
            #pragma unroll
            for (int i = 0; i < 4; i++) {
                float4 v = __ldg(xr + i);
                uint32_t h0, l0, h1, l1;
                split_pair(v.x, v.y, h0, l0);
                split_pair(v.z, v.w, h1, l1);
                xth[wbase + i * 2] = h0; xth[wbase + i * 2 + 1] = h1;
                xtl[wbase + i * 2] = l0; xtl[wbase + i * 2 + 1] = l1;
            }
        }
        __syncthreads();

        float cc[8][4];
        #pragma unroll
        for (int n = 0; n < 8; n++) {
            cc[n][0] = bv0; cc[n][1] = bv0; cc[n][2] = bv1; cc[n][3] = bv1;
        }
        for (int ks = 0; ks < 8; ks++) {
            uint32_t ah[4], al[4];
            #pragma unroll
            for (int r = 0; r < 4; r++) {
                ah[r] = wp[ks * 256 + r * 32];
                al[r] = wp[ks * 256 + 128 + r * 32];
            }
            #pragma unroll
            for (int n = 0; n < 8; n++) {
                int wd = (n * 8 + grp) * 68 + ks * 8 + tk;
                uint32_t bh0 = xth[wd], bh1 = xth[wd + 4];
                uint32_t bl0 = xtl[wd], bl1 = xtl[wd + 4];
                MMA(cc[n], ah, bh0, bh1);
                MMA(cc[n], ah, bl0, bl1);
                MMA(cc[n], al, bh0, bh1);
            }
        }
        // store: warp block of 1024 floats; value-group n at n*128 + lane*4
        float* op = g_xg + ((((size_t)(d * 128 + blk) * 50 + m) * 16 + w) * 8) * 128 + lid * 4;
        #pragma unroll
        for (int n = 0; n < 8; n++) {
            float4 v;
            v.x = cc[n][0]; v.y = cc[n][1]; v.z = cc[n][2]; v.w = cc[n][3];
            *(float4*)(op + n * 128) = v;
        }
        __syncthreads();
    }
}

// ===========================================================================
// k_layer2: BiLSTM layer 2 recurrence (mma) + fc2 + tanh; xg from g_xg
// (unchanged from round 10 — validated at 890us)
// ===========================================================================
#define HT_HI 0
#define HT_LO 9216
#define GACTO 18432
#define HBUFO 84992
#define OUTAO 102400
#define L2_SM 128000

__global__ __launch_bounds__(512, 1)
void k_layer2(const float* __restrict__ fc2_w, const float* __restrict__ fc2_b,
              float* __restrict__ out)
{
    extern __shared__ char smc[];
    uint32_t* hth = (uint32_t*)(smc + HT_HI);
    uint32_t* htl = (uint32_t*)(smc + HT_LO);
    float*    ga  = (float*)(smc + GACTO);
    float*    hbf = (float*)(smc + HBUFO);
    float*    oa  = (float*)(smc + OUTAO);

    const int tid = threadIdx.x;
    const int w   = tid >> 5, lid = tid & 31;
    const int grp = lid >> 2, tk = lid & 3;
    const int j = tid & 63, q = tid >> 6;
    const int blk = blockIdx.x;
    const float fc2bv = __ldg(fc2_b);

    for (int d = 0; d < 2; d++) {
        const float fwa = __ldg(&fc2_w[d * 64 + lid]);
        const float fwb = __ldg(&fc2_w[d * 64 + 32 + lid]);

        uint32_t wa[32];
        {
            const uint32_t* hp = g_whhf + (d * 16 + w) * 4 * 256 + lid;
            #pragma unroll
            for (int ks = 0; ks < 4; ks++)
                #pragma unroll
                for (int tm = 0; tm < 2; tm++)
                    #pragma unroll
                    for (int r = 0; r < 4; r++)
                        wa[(ks * 2 + tm) * 4 + r] = __ldg(hp + (ks * 2 + tm) * 128 + r * 32);
        }

        __syncthreads();
        for (int p = tid; p < 4608; p += 512) hth[p] = 0u;
        float c8[8];
        #pragma unroll
        for (int i = 0; i < 8; i++) c8[i] = 0.f;

        float xgv[32];
        {
            const int m0 = d ? 49 : 0;
            const float* xp = g_xg + ((((size_t)(d * 128 + blk) * 50 + m0) * 16 + w) * 8) * 128 + lid * 4;
            #pragma unroll
            for (int n = 0; n < 8; n++) {
                float4 v = __ldg((const float4*)(xp + n * 128));
                xgv[n * 4 + 0] = v.x; xgv[n * 4 + 1] = v.y;
                xgv[n * 4 + 2] = v.z; xgv[n * 4 + 3] = v.w;
            }
        }
        __syncthreads();

        for (int tt = 0; tt < T2; tt++) {
            const int t = d ? (T2 - 1 - tt) : tt;

            float cc[8][4];
            #pragma unroll
            for (int n = 0; n < 8; n++)
                #pragma unroll
                for (int r = 0; r < 4; r++) cc[n][r] = xgv[n * 4 + r];

            if (tt & 1) {
                const int m  = t >> 1;
                const int mn = d ? (m - 1) : (m + 1);
                if (mn >= 0 && mn < 50) {
                    const float* xp = g_xg + ((((size_t)(d * 128 + blk) * 50 + mn) * 16 + w) * 8) * 128 + lid * 4;
                    #pragma unroll
                    for (int n = 0; n < 8; n++) {
                        float4 v = __ldg((const float4*)(xp + n * 128));
                        xgv[n * 4 + 0] = v.x; xgv[n * 4 + 1] = v.y;
                        xgv[n * 4 + 2] = v.z; xgv[n * 4 + 3] = v.w;
                    }
                }
            }

            #pragma unroll
            for (int ks = 0; ks < 4; ks++) {
                #pragma unroll
                for (int n = 0; n < 8; n++) {
                    int wd = (n * 8 + grp) * 36 + ks * 8 + tk;
                    uint32_t bh0 = hth[wd], bh1 = hth[wd + 4];
                    uint32_t bl0 = htl[wd], bl1 = htl[wd + 4];
                    MMA(cc[n], &wa[(ks * 2 + 0) * 4], bh0, bh1);
                    MMA(cc[n], &wa[(ks * 2 + 0) * 4], bl0, bl1);
                    MMA(cc[n], &wa[(ks * 2 + 1) * 4], bh0, bh1);
                }
            }

            #pragma unroll
            for (int n = 0; n < 8; n++) {
                int s0 = n * 8 + 2 * tk, gcol = w * 16 + grp;
                ga[s0 * 260 + gcol]           = cc[n][0];
                ga[(s0 + 1) * 260 + gcol]     = cc[n][1];
                ga[s0 * 260 + gcol + 8]       = cc[n][2];
                ga[(s0 + 1) * 260 + gcol + 8] = cc[n][3];
            }
            __syncthreads();

            #pragma unroll
            for (int si = 0; si < 8; si++) {
                const int s = q + si * 8;
                float gi = ga[s * 260 + j],       gf = ga[s * 260 + 64 + j];
                float gg = ga[s * 260 + 128 + j], go = ga[s * 260 + 192 + j];
                float c = fmaf(fsig(gf), c8[si], fsig(gi) * ftanh_(gg));
                c8[si] = c;
                float h = fsig(go) * ftanh_(c);
                hbf[s * 68 + j] = h;
                __nv_bfloat16 hh = __float2bfloat16_rn(h);
                __nv_bfloat16 hl = __float2bfloat16_rn(h - __bfloat162float(hh));
                ((__nv_bfloat16*)hth)[s * 72 + j] = hh;
                ((__nv_bfloat16*)htl)[s * 72 + j] = hl;
            }
            __syncthreads();

            #pragma unroll
            for (int si2 = 0; si2 < 4; si2++) {
                const int s = w * 4 + si2;
                float pm = hbf[s * 68 + lid] * fwa + hbf[s * 68 + 32 + lid] * fwb;
                #pragma unroll
                for (int o = 16; o > 0; o >>= 1)
                    pm += __shfl_down_sync(0xffffffffu, pm, o);
                if (lid == 0) {
                    if (d == 0) oa[s * 100 + t] = pm;
                    else out[(size_t)(blk * 64 + s) * T2 + t] = ftanh_(oa[s * 100 + t] + pm + fc2bv);
                }
            }
        }
    }
}

// ---------------------------------------------------------------------------
extern "C" void kernel_launch(void* const* d_in, const int* in_sizes, int n_in,
                              void* d_out, int out_size)
{
    const float* x    = (const float*)d_in[0];
    const float* fc1w = (const float*)d_in[1];
    const float* fc1b = (const float*)d_in[2];
    const float* r1wf = (const float*)d_in[3];
    const float* r1hf = (const float*)d_in[4];
    const float* r1bf = (const float*)d_in[5];
    const float* r1wb = (const float*)d_in[6];
    const float* r1hb = (const float*)d_in[7];
    const float* r1bb = (const float*)d_in[8];
    const float* r2wf = (const float*)d_in[9];
    const float* r2hf = (const float*)d_in[10];
    const float* r2bf = (const float*)d_in[11];
    const float* r2wb = (const float*)d_in[12];
    const float* r2hb = (const float*)d_in[13];
    const float* r2bb = (const float*)d_in[14];
    const float* fc2w = (const float*)d_in[15];
    const float* fc2b = (const float*)d_in[16];
    float* out = (float*)d_out;

    const size_t SM1 = (size_t)(G1 * GA_P + G1 * HB_P + G1 * T1) * sizeof(float);

    cudaFuncSetAttribute(k_layer1, cudaFuncAttributeMaxDynamicSharedMemorySize, (int)SM1);
    cudaFuncSetAttribute(k_proj,   cudaFuncAttributeMaxDynamicSharedMemorySize, PJ_SM);
    cudaFuncSetAttribute(k_layer2, cudaFuncAttributeMaxDynamicSharedMemorySize, L2_SM);

    k_prep<<<64, 256>>>(r2wf, r2wb, r2hf, r2hb);
    k_layer1<<<BT / G1, 256, SM1>>>(x, fc1w, fc1b, r1wf, r1hf, r1bf, r1wb, r1hb, r1bb);
    k_proj<<<512, 512, PJ_SM>>>(r2bf, r2bb);
    k_layer2<<<128, 512, L2_SM>>>(fc2w, fc2b, out);
}

// round 13
// speedup vs baseline: 1.1477x; 1.0719x over previous
#include <cuda_runtime.h>
#include <cuda_bf16.h>
#include <cstdint>

#define BT 8192
#define T1 50
#define T2 100
#define G1 32
#define HB_P 68
#define GA_P 260

static __device__ float g_seq1[BT * T1 * 128];
static __device__ uint32_t g_wihf[2 * 16 * 8 * 2 * 4 * 32];   // layer2 Wih frags
static __device__ uint32_t g_whhf[2 * 16 * 4 * 2 * 4 * 32];   // layer2 Whh frags
static __device__ float g_xg[2 * 128 * 50 * 16 * 1024];       // proj results (839MB)

__device__ __forceinline__ float fsig(float x) {
    return __fdividef(1.f, 1.f + __expf(-x));
}
__device__ __forceinline__ float ftanh_(float x) {
    float e = __expf(-2.f * fabsf(x));
    float r = __fdividef(1.f - e, 1.f + e);
    return copysignf(r, x);
}
// fast activations: single-MUFU tanh.approx (internal gates only)
__device__ __forceinline__ float tanh_fast(float x) {
    float y;
    asm("tanh.approx.f32 %0, %1;" : "=f"(y) : "f"(x));
    return y;
}
__device__ __forceinline__ float sig_fast(float x) {
    return fmaf(tanh_fast(0.5f * x), 0.5f, 0.5f);
}
__device__ __forceinline__ float dot4acc(float4 w, float4 h, float a) {
    a = fmaf(w.x, h.x, a); a = fmaf(w.y, h.y, a);
    a = fmaf(w.z, h.z, a); return fmaf(w.w, h.w, a);
}
__device__ __forceinline__ uint32_t pack_bf2(float v0, float v1) {
    __nv_bfloat162 t = __floats2bfloat162_rn(v0, v1);
    return *(uint32_t*)&t;
}
__device__ __forceinline__ void split_pair(float v0, float v1, uint32_t& hi, uint32_t& lo) {
    __nv_bfloat16 h0 = __float2bfloat16_rn(v0), h1 = __float2bfloat16_rn(v1);
    hi = ((uint32_t)*(uint16_t*)&h1 << 16) | *(uint16_t*)&h0;
    lo = pack_bf2(v0 - __bfloat162float(h0), v1 - __bfloat162float(h1));
}
#define MMA(c, a, b0, b1) \
    asm volatile("mma.sync.aligned.m16n8k16.row.col.f32.bf16.bf16.f32 " \
                 "{%0,%1,%2,%3},{%4,%5,%6,%7},{%8,%9},{%0,%1,%2,%3};" \
                 : "+f"((c)[0]), "+f"((c)[1]), "+f"((c)[2]), "+f"((c)[3]) \
                 : "r"((a)[0]), "r"((a)[1]), "r"((a)[2]), "r"((a)[3]), "r"(b0), "r"(b1))

// ===========================================================================
// k_prep: pre-split layer2 weights into A-fragment layout (parallel)
// frag (r,lane): row = w*16 + (lane>>2) + (r&1)*8, col = ks*16 + ((r>>1)&1)*8 + (lane&3)*2
// ===========================================================================
__global__ void k_prep(const float* __restrict__ wf, const float* __restrict__ wb,
                       const float* __restrict__ hf, const float* __restrict__ hb)
{
    const int gt = blockIdx.x * blockDim.x + threadIdx.x;
    const int nt = gridDim.x * blockDim.x;
    for (int e = gt; e < 2 * 16 * 8 * 4 * 32; e += nt) {
        int l = e & 31, r = (e >> 5) & 3, ks = (e >> 7) & 7, w = (e >> 10) & 15, d = e >> 14;
        const float* W = d ? wb : wf;
        int row = w * 16 + (l >> 2) + (r & 1) * 8;
        int col = ks * 16 + ((r >> 1) & 1) * 8 + (l & 3) * 2;
        uint32_t hi, lo;
        split_pair(W[row * 128 + col], W[row * 128 + col + 1], hi, lo);
        uint32_t base = (((d * 16 + w) * 8 + ks) * 2) * 128 + r * 32 + l;
        g_wihf[base] = hi; g_wihf[base + 128] = lo;
    }
    for (int e = gt; e < 2 * 16 * 4 * 4 * 32; e += nt) {
        int l = e & 31, r = (e >> 5) & 3, ks = (e >> 7) & 3, w = (e >> 9) & 15, d = e >> 13;
        const float* W = d ? hb : hf;
        int row = w * 16 + (l >> 2) + (r & 1) * 8;
        int col = ks * 16 + ((r >> 1) & 1) * 8 + (l & 3) * 2;
        uint32_t hi, lo;
        split_pair(W[row * 64 + col], W[row * 64 + col + 1], hi, lo);
        uint32_t base = (((d * 16 + w) * 4 + ks) * 2) * 128 + r * 32 + l;
        g_whhf[base] = hi; g_whhf[base + 128] = lo;
    }
}

// ===========================================================================
// k_layer1: fc1 + BiLSTM layer 1 (FFMA; fast activations)
// ===========================================================================
__global__ __launch_bounds__(256, 2)
void k_layer1(const float* __restrict__ x,
              const float* __restrict__ fc1_w, const float* __restrict__ fc1_b,
              const float* __restrict__ wih_f, const float* __restrict__ whh_f, const float* __restrict__ b_f,
              const float* __restrict__ wih_b, const float* __restrict__ whh_b, const float* __restrict__ b_b)
{
    extern __shared__ float sm[];
    float* gact  = sm;
    float* hbuf  = gact + G1 * GA_P;
    float* h1buf = hbuf + G1 * HB_P;

    const int tid  = threadIdx.x;
    const int base = blockIdx.x * G1;
    const int g    = tid;
    const int j    = tid & 63, q = tid >> 6;

    for (int idx = tid; idx < G1 * T1; idx += 256) {
        int s = idx / T1, t = idx - s * T1;
        const float* xr = x + (base + s) * 20;
        const float* wr = fc1_w + t * 20;
        float acc = fc1_b[t];
        #pragma unroll
        for (int i = 0; i < 20; i++) acc = fmaf(xr[i], wr[i], acc);
        h1buf[s * T1 + t] = acc;
    }

    for (int d = 0; d < 2; d++) {
        const float* whh = d ? whh_b : whh_f;
        const float* wih = d ? wih_b : wih_f;
        const float* bg  = d ? b_b   : b_f;

        __syncthreads();
        for (int idx = tid; idx < G1 * HB_P; idx += 256) hbuf[idx] = 0.f;

        float4 wv[16];
        const float4* wgp = (const float4*)(whh + g * 64);
        #pragma unroll
        for (int kc = 0; kc < 16; kc++) wv[kc] = __ldg(wgp + kc);
        const float wihg = __ldg(wih + g);
        const float bsg  = __ldg(bg + g);

        float c_reg[8];
        #pragma unroll
        for (int i = 0; i < 8; i++) c_reg[i] = 0.f;
        __syncthreads();

        const bool tanh_gate = ((g >> 6) == 2);

        for (int tt = 0; tt < T1; tt++) {
            const int t = d ? (T1 - 1 - tt) : tt;
            for (int sg = 0; sg < G1; sg += 2) {
                float a0 = fmaf(h1buf[(sg + 0) * T1 + t], wihg, bsg);
                float a1 = fmaf(h1buf[(sg + 1) * T1 + t], wihg, bsg);
                #pragma unroll
                for (int kc = 0; kc < 16; kc++) {
                    float4 w4 = wv[kc];
                    float4 h0 = *(const float4*)(hbuf + (sg + 0) * HB_P + kc * 4);
                    float4 h1 = *(const float4*)(hbuf + (sg + 1) * HB_P + kc * 4);
                    a0 = dot4acc(w4, h0, a0);
                    a1 = dot4acc(w4, h1, a1);
                }
                gact[(sg + 0) * GA_P + g] = tanh_gate ? tanh_fast(a0) : sig_fast(a0);
                gact[(sg + 1) * GA_P + g] = tanh_gate ? tanh_fast(a1) : sig_fast(a1);
            }
            __syncthreads();
            #pragma unroll
            for (int si = 0; si < 8; si++) {
                const int s = q + si * 4;
                float gi = gact[s * GA_P + j];
                float gf = gact[s * GA_P + 64 + j];
                float gg = gact[s * GA_P + 128 + j];
                float go = gact[s * GA_P + 192 + j];
                float c  = fmaf(gf, c_reg[si], gi * gg);
                c_reg[si] = c;
                float h = go * tanh_fast(c);
                hbuf[s * HB_P + j] = h;
                g_seq1[((base + s) * T1 + t) * 128 + d * 64 + j] = h;
            }
            __syncthreads();
        }
    }
}

// ===========================================================================
// k_proj v3: double-buffered x staging (LDG prefetch hides under MMA)
// grid = (d, blk, half) = 512 CTAs x 25 m each
// ===========================================================================
#define PJ_W  0                         // 128KB weight frags
#define PJ_X  131072                    // 2 buffers x (hi 17408 + lo 17408)
#define PJ_SM (131072 + 69632)

__global__ __launch_bounds__(512, 1)
void k_proj(const float* __restrict__ b2_f, const float* __restrict__ b2_b)
{
    extern __shared__ char smc[];
    uint32_t* wsm = (uint32_t*)(smc + PJ_W);

    const int tid = threadIdx.x;
    const int w   = tid >> 5, lid = tid & 31;
    const int grp = lid >> 2, tk = lid & 3;
    const int bi  = blockIdx.x;
    const int d   = bi >> 8, blk = (bi >> 1) & 127, half = bi & 1;
    const int m0  = half * 25;

    const float* bg = d ? b2_b : b2_f;
    const float bv0 = __ldg(&bg[w * 16 + grp]);
    const float bv1 = __ldg(&bg[w * 16 + grp + 8]);

    // stage this d's Wih fragments into SMEM once
    {
        const uint32_t* src = g_wihf + d * 32768;
        for (int p = tid; p < 32768; p += 512) wsm[p] = __ldg(src + p);
    }
    const uint32_t* wp = wsm + w * 2048 + lid;

    // x staging geometry (per thread: 1 row-segment of 16 floats)
    const int srow = tid >> 3, f0 = (tid & 7) * 16;
    const int wbase = srow * 68 + (f0 >> 1);

    // prefetch m0
    float4 xr[4];
    {
        const float4* p = (const float4*)(g_seq1 +
            ((size_t)(blk * 64 + srow) * T1 + m0) * 128 + f0);
        #pragma unroll
        for (int i = 0; i < 4; i++) xr[i] = __ldg(p + i);
    }
    __syncthreads();

    for (int mi = 0; mi < 25; mi++) {
        const int m = m0 + mi;
        uint32_t* xth = (uint32_t*)(smc + PJ_X + (mi & 1) * 34816);
        uint32_t* xtl = xth + 4352;

        // split prefetched regs -> current buffer
        #pragma unroll
        for (int i = 0; i < 4; i++) {
            uint32_t h0, l0, h1, l1;
            split_pair(xr[i].x, xr[i].y, h0, l0);
            split_pair(xr[i].z, xr[i].w, h1, l1);
            xth[wbase + i * 2] = h0; xth[wbase + i * 2 + 1] = h1;
            xtl[wbase + i * 2] = l0; xtl[wbase + i * 2 + 1] = l1;
        }
        __syncthreads();

        // prefetch next chunk (latency hides under the MMA block below)
        if (mi < 24) {
            const float4* p = (const float4*)(g_seq1 +
                ((size_t)(blk * 64 + srow) * T1 + (m + 1)) * 128 + f0);
            #pragma unroll
            for (int i = 0; i < 4; i++) xr[i] = __ldg(p + i);
        }

        float cc[8][4];
        #pragma unroll
        for (int n = 0; n < 8; n++) {
            cc[n][0] = bv0; cc[n][1] = bv0; cc[n][2] = bv1; cc[n][3] = bv1;
        }
        for (int ks = 0; ks < 8; ks++) {
            uint32_t ah[4], al[4];
            #pragma unroll
            for (int r = 0; r < 4; r++) {
                ah[r] = wp[ks * 256 + r * 32];
                al[r] = wp[ks * 256 + 128 + r * 32];
            }
            #pragma unroll
            for (int n = 0; n < 8; n++) {
                int wd = (n * 8 + grp) * 68 + ks * 8 + tk;
                uint32_t bh0 = xth[wd], bh1 = xth[wd + 4];
                uint32_t bl0 = xtl[wd], bl1 = xtl[wd + 4];
                MMA(cc[n], ah, bh0, bh1);
                MMA(cc[n], ah, bl0, bl1);
                MMA(cc[n], al, bh0, bh1);
            }
        }
        float* op = g_xg + ((((size_t)(d * 128 + blk) * 50 + m) * 16 + w) * 8) * 128 + lid * 4;
        #pragma unroll
        for (int n = 0; n < 8; n++) {
            float4 v;
            v.x = cc[n][0]; v.y = cc[n][1]; v.z = cc[n][2]; v.w = cc[n][3];
            *(float4*)(op + n * 128) = v;
        }
        __syncthreads();
    }
}

// ===========================================================================
// k_layer2: BiLSTM layer 2 recurrence (mma) + fc2 + tanh (fast gate acts)
// ===========================================================================
#define HT_HI 0
#define HT_LO 9216
#define GACTO 18432
#define HBUFO 84992
#define OUTAO 102400
#define L2_SM 128000

__global__ __launch_bounds__(512, 1)
void k_layer2(const float* __restrict__ fc2_w, const float* __restrict__ fc2_b,
              float* __restrict__ out)
{
    extern __shared__ char smc[];
    uint32_t* hth = (uint32_t*)(smc + HT_HI);
    uint32_t* htl = (uint32_t*)(smc + HT_LO);
    float*    ga  = (float*)(smc + GACTO);
    float*    hbf = (float*)(smc + HBUFO);
    float*    oa  = (float*)(smc + OUTAO);

    const int tid = threadIdx.x;
    const int w   = tid >> 5, lid = tid & 31;
    const int grp = lid >> 2, tk = lid & 3;
    const int j = tid & 63, q = tid >> 6;
    const int blk = blockIdx.x;
    const float fc2bv = __ldg(fc2_b);

    for (int d = 0; d < 2; d++) {
        const float fwa = __ldg(&fc2_w[d * 64 + lid]);
        const float fwb = __ldg(&fc2_w[d * 64 + 32 + lid]);

        uint32_t wa[32];
        {
            const uint32_t* hp = g_whhf + (d * 16 + w) * 4 * 256 + lid;
            #pragma unroll
            for (int ks = 0; ks < 4; ks++)
                #pragma unroll
                for (int tm = 0; tm < 2; tm++)
                    #pragma unroll
                    for (int r = 0; r < 4; r++)
                        wa[(ks * 2 + tm) * 4 + r] = __ldg(hp + (ks * 2 + tm) * 128 + r * 32);
        }

        __syncthreads();
        for (int p = tid; p < 4608; p += 512) hth[p] = 0u;
        float c8[8];
        #pragma unroll
        for (int i = 0; i < 8; i++) c8[i] = 0.f;

        float xgv[32];
        {
            const int m0 = d ? 49 : 0;
            const float* xp = g_xg + ((((size_t)(d * 128 + blk) * 50 + m0) * 16 + w) * 8) * 128 + lid * 4;
            #pragma unroll
            for (int n = 0; n < 8; n++) {
                float4 v = __ldg((const float4*)(xp + n * 128));
                xgv[n * 4 + 0] = v.x; xgv[n * 4 + 1] = v.y;
                xgv[n * 4 + 2] = v.z; xgv[n * 4 + 3] = v.w;
            }
        }
        __syncthreads();

        for (int tt = 0; tt < T2; tt++) {
            const int t = d ? (T2 - 1 - tt) : tt;

            float cc[8][4];
            #pragma unroll
            for (int n = 0; n < 8; n++)
                #pragma unroll
                for (int r = 0; r < 4; r++) cc[n][r] = xgv[n * 4 + r];

            if (tt & 1) {
                const int m  = t >> 1;
                const int mn = d ? (m - 1) : (m + 1);
                if (mn >= 0 && mn < 50) {
                    const float* xp = g_xg + ((((size_t)(d * 128 + blk) * 50 + mn) * 16 + w) * 8) * 128 + lid * 4;
                    #pragma unroll
                    for (int n = 0; n < 8; n++) {
                        float4 v = __ldg((const float4*)(xp + n * 128));
                        xgv[n * 4 + 0] = v.x; xgv[n * 4 + 1] = v.y;
                        xgv[n * 4 + 2] = v.z; xgv[n * 4 + 3] = v.w;
                    }
                }
            }

            #pragma unroll
            for (int ks = 0; ks < 4; ks++) {
                #pragma unroll
                for (int n = 0; n < 8; n++) {
                    int wd = (n * 8 + grp) * 36 + ks * 8 + tk;
                    uint32_t bh0 = hth[wd], bh1 = hth[wd + 4];
                    uint32_t bl0 = htl[wd], bl1 = htl[wd + 4];
                    MMA(cc[n], &wa[(ks * 2 + 0) * 4], bh0, bh1);
                    MMA(cc[n], &wa[(ks * 2 + 0) * 4], bl0, bl1);
                    MMA(cc[n], &wa[(ks * 2 + 1) * 4], bh0, bh1);
                }
            }

            #pragma unroll
            for (int n = 0; n < 8; n++) {
                int s0 = n * 8 + 2 * tk, gcol = w * 16 + grp;
                ga[s0 * 260 + gcol]           = cc[n][0];
                ga[(s0 + 1) * 260 + gcol]     = cc[n][1];
                ga[s0 * 260 + gcol + 8]       = cc[n][2];
                ga[(s0 + 1) * 260 + gcol + 8] = cc[n][3];
            }
            __syncthreads();

            #pragma unroll
            for (int si = 0; si < 8; si++) {
                const int s = q + si * 8;
                float gi = ga[s * 260 + j],       gf = ga[s * 260 + 64 + j];
                float gg = ga[s * 260 + 128 + j], go = ga[s * 260 + 192 + j];
                float c = fmaf(sig_fast(gf), c8[si], sig_fast(gi) * tanh_fast(gg));
                c8[si] = c;
                float h = sig_fast(go) * tanh_fast(c);
                hbf[s * 68 + j] = h;
                __nv_bfloat16 hh = __float2bfloat16_rn(h);
                __nv_bfloat16 hl = __float2bfloat16_rn(h - __bfloat162float(hh));
                ((__nv_bfloat16*)hth)[s * 72 + j] = hh;
                ((__nv_bfloat16*)htl)[s * 72 + j] = hl;
            }
            __syncthreads();

            #pragma unroll
            for (int si2 = 0; si2 < 4; si2++) {
                const int s = w * 4 + si2;
                float pm = hbf[s * 68 + lid] * fwa + hbf[s * 68 + 32 + lid] * fwb;
                #pragma unroll
                for (int o = 16; o > 0; o >>= 1)
                    pm += __shfl_down_sync(0xffffffffu, pm, o);
                if (lid == 0) {
                    if (d == 0) oa[s * 100 + t] = pm;
                    else out[(size_t)(blk * 64 + s) * T2 + t] = ftanh_(oa[s * 100 + t] + pm + fc2bv);
                }
            }
        }
    }
}

// ---------------------------------------------------------------------------
extern "C" void kernel_launch(void* const* d_in, const int* in_sizes, int n_in,
                              void* d_out, int out_size)
{
    const float* x    = (const float*)d_in[0];
    const float* fc1w = (const float*)d_in[1];
    const float* fc1b = (const float*)d_in[2];
    const float* r1wf = (const float*)d_in[3];
    const float* r1hf = (const float*)d_in[4];
    const float* r1bf = (const float*)d_in[5];
    const float* r1wb = (const float*)d_in[6];
    const float* r1hb = (const float*)d_in[7];
    const float* r1bb = (const float*)d_in[8];
    const float* r2wf = (const float*)d_in[9];
    const float* r2hf = (const float*)d_in[10];
    const float* r2bf = (const float*)d_in[11];
    const float* r2wb = (const float*)d_in[12];
    const float* r2hb = (const float*)d_in[13];
    const float* r2bb = (const float*)d_in[14];
    const float* fc2w = (const float*)d_in[15];
    const float* fc2b = (const float*)d_in[16];
    float* out = (float*)d_out;

    const size_t SM1 = (size_t)(G1 * GA_P + G1 * HB_P + G1 * T1) * sizeof(float);

    cudaFuncSetAttribute(k_layer1, cudaFuncAttributeMaxDynamicSharedMemorySize, (int)SM1);
    cudaFuncSetAttribute(k_proj,   cudaFuncAttributeMaxDynamicSharedMemorySize, PJ_SM);
    cudaFuncSetAttribute(k_layer2, cudaFuncAttributeMaxDynamicSharedMemorySize, L2_SM);

    k_prep<<<64, 256>>>(r2wf, r2wb, r2hf, r2hb);
    k_layer1<<<BT / G1, 256, SM1>>>(x, fc1w, fc1b, r1wf, r1hf, r1bf, r1wb, r1hb, r1bb);
    k_proj<<<512, 512, PJ_SM>>>(r2bf, r2bb);
    k_layer2<<<128, 512, L2_SM>>>(fc2w, fc2b, out);
}

// round 14
// speedup vs baseline: 1.5683x; 1.3665x over previous
#include <cuda_runtime.h>
#include <cuda_bf16.h>
#include <cstdint>

#define BT 8192
#define T1 50
#define T2 100

static __device__ float g_seq1[BT * T1 * 128];
static __device__ uint32_t g_wihf[2 * 16 * 8 * 2 * 4 * 32];   // layer2 Wih frags
static __device__ uint32_t g_whhf[2 * 16 * 4 * 2 * 4 * 32];   // layer2 Whh frags
static __device__ uint32_t g_whh1f[2 * 16 * 4 * 2 * 4 * 32];  // layer1 Whh frags
static __device__ float g_xg[2 * 128 * 50 * 16 * 1024];       // proj results (839MB)

__device__ __forceinline__ float ftanh_(float x) {
    float e = __expf(-2.f * fabsf(x));
    float r = __fdividef(1.f - e, 1.f + e);
    return copysignf(r, x);
}
// fast activations: single-MUFU tanh.approx (internal gates only)
__device__ __forceinline__ float tanh_fast(float x) {
    float y;
    asm("tanh.approx.f32 %0, %1;" : "=f"(y) : "f"(x));
    return y;
}
__device__ __forceinline__ float sig_fast(float x) {
    return fmaf(tanh_fast(0.5f * x), 0.5f, 0.5f);
}
__device__ __forceinline__ uint32_t pack_bf2(float v0, float v1) {
    __nv_bfloat162 t = __floats2bfloat162_rn(v0, v1);
    return *(uint32_t*)&t;
}
__device__ __forceinline__ void split_pair(float v0, float v1, uint32_t& hi, uint32_t& lo) {
    __nv_bfloat16 h0 = __float2bfloat16_rn(v0), h1 = __float2bfloat16_rn(v1);
    hi = ((uint32_t)*(uint16_t*)&h1 << 16) | *(uint16_t*)&h0;
    lo = pack_bf2(v0 - __bfloat162float(h0), v1 - __bfloat162float(h1));
}
#define MMA(c, a, b0, b1) \
    asm volatile("mma.sync.aligned.m16n8k16.row.col.f32.bf16.bf16.f32 " \
                 "{%0,%1,%2,%3},{%4,%5,%6,%7},{%8,%9},{%0,%1,%2,%3};" \
                 : "+f"((c)[0]), "+f"((c)[1]), "+f"((c)[2]), "+f"((c)[3]) \
                 : "r"((a)[0]), "r"((a)[1]), "r"((a)[2]), "r"((a)[3]), "r"(b0), "r"(b1))

// ===========================================================================
// k_prep: pre-split weights into A-fragment layout (parallel)
// frag (r,lane): row = w*16 + (lane>>2) + (r&1)*8, col = ks*16 + ((r>>1)&1)*8 + (lane&3)*2
// ===========================================================================
__global__ void k_prep(const float* __restrict__ wf, const float* __restrict__ wb,
                       const float* __restrict__ hf, const float* __restrict__ hb,
                       const float* __restrict__ h1f, const float* __restrict__ h1b)
{
    const int gt = blockIdx.x * blockDim.x + threadIdx.x;
    const int nt = gridDim.x * blockDim.x;
    for (int e = gt; e < 2 * 16 * 8 * 4 * 32; e += nt) {
        int l = e & 31, r = (e >> 5) & 3, ks = (e >> 7) & 7, w = (e >> 10) & 15, d = e >> 14;
        const float* W = d ? wb : wf;
        int row = w * 16 + (l >> 2) + (r & 1) * 8;
        int col = ks * 16 + ((r >> 1) & 1) * 8 + (l & 3) * 2;
        uint32_t hi, lo;
        split_pair(W[row * 128 + col], W[row * 128 + col + 1], hi, lo);
        uint32_t base = (((d * 16 + w) * 8 + ks) * 2) * 128 + r * 32 + l;
        g_wihf[base] = hi; g_wihf[base + 128] = lo;
    }
    for (int e = gt; e < 2 * 16 * 4 * 4 * 32; e += nt) {
        int l = e & 31, r = (e >> 5) & 3, ks = (e >> 7) & 3, w = (e >> 9) & 15, d = e >> 13;
        int row = w * 16 + (l >> 2) + (r & 1) * 8;
        int col = ks * 16 + ((r >> 1) & 1) * 8 + (l & 3) * 2;
        uint32_t base = (((d * 16 + w) * 4 + ks) * 2) * 128 + r * 32 + l;
        uint32_t hi, lo;
        const float* W2 = d ? hb : hf;
        split_pair(W2[row * 64 + col], W2[row * 64 + col + 1], hi, lo);
        g_whhf[base] = hi; g_whhf[base + 128] = lo;
        const float* W1 = d ? h1b : h1f;
        split_pair(W1[row * 64 + col], W1[row * 64 + col + 1], hi, lo);
        g_whh1f[base] = hi; g_whh1f[base + 128] = lo;
    }
}

// ===========================================================================
// k_layer1: fc1 + BiLSTM layer 1 on mma.sync -> g_seq1
// CTA = 64 samples, 16 warps; warp w = gates [w*16, w*16+16).
// Input projection is rank-1 (input dim 1): folded into C-fragment init.
// Minimal-diff retry of round 9 (only delta: fast activations).
// ===========================================================================
#define L1_H1  0                     // h1buf [64][52] fp32   = 13312B
#define L1_HTH 13312                 // hT hi [64][36] words  =  9216B
#define L1_HTL 22528                 // hT lo                 =  9216B
#define L1_GA  31744                 // gact [64][260] fp32   = 66560B
#define L1_SM  98304

__global__ __launch_bounds__(512, 1)
void k_layer1(const float* __restrict__ x,
              const float* __restrict__ fc1_w, const float* __restrict__ fc1_b,
              const float* __restrict__ wih_f, const float* __restrict__ b_f,
              const float* __restrict__ wih_b, const float* __restrict__ b_b)
{
    extern __shared__ char smc[];
    float*    h1  = (float*)(smc + L1_H1);
    uint32_t* hth = (uint32_t*)(smc + L1_HTH);
    uint32_t* htl = (uint32_t*)(smc + L1_HTL);
    float*    ga  = (float*)(smc + L1_GA);

    const int tid = threadIdx.x;
    const int w   = tid >> 5, lid = tid & 31;
    const int grp = lid >> 2, tk = lid & 3;
    const int j = tid & 63, q = tid >> 6;
    const int blk = blockIdx.x;

    // fc1: h1[s][t] = x[s] . fc1_w[t] + fc1_b[t]
    for (int idx = tid; idx < 64 * T1; idx += 512) {
        int s = idx / T1, t = idx - s * T1;
        const float* xr = x + (size_t)(blk * 64 + s) * 20;
        const float* wr = fc1_w + t * 20;
        float acc = __ldg(&fc1_b[t]);
        #pragma unroll
        for (int i = 0; i < 20; i++) acc = fmaf(__ldg(xr + i), __ldg(wr + i), acc);
        h1[s * 52 + t] = acc;
    }

    for (int d = 0; d < 2; d++) {
        const float* bg  = d ? b_b : b_f;
        const float* wih = d ? wih_b : wih_f;
        const float bv0 = __ldg(&bg[w * 16 + grp]);
        const float bv1 = __ldg(&bg[w * 16 + grp + 8]);
        const float wi0 = __ldg(&wih[w * 16 + grp]);
        const float wi1 = __ldg(&wih[w * 16 + grp + 8]);

        // resident Whh A-fragments
        uint32_t wa[32];
        {
            const uint32_t* hp = g_whh1f + (d * 16 + w) * 4 * 256 + lid;
            #pragma unroll
            for (int ks = 0; ks < 4; ks++)
                #pragma unroll
                for (int tm = 0; tm < 2; tm++)
                    #pragma unroll
                    for (int r = 0; r < 4; r++)
                        wa[(ks * 2 + tm) * 4 + r] = __ldg(hp + (ks * 2 + tm) * 128 + r * 32);
        }

        __syncthreads();
        for (int p = tid; p < 4608; p += 512) hth[p] = 0u;   // hth+htl contiguous
        float c8[8];
        #pragma unroll
        for (int i = 0; i < 8; i++) c8[i] = 0.f;
        __syncthreads();

        for (int tt = 0; tt < T1; tt++) {
            const int t = d ? (T1 - 1 - tt) : tt;

            // C init = bias + wih * h1 (rank-1 input projection)
            float cc[8][4];
            #pragma unroll
            for (int n = 0; n < 8; n++) {
                int s0 = n * 8 + 2 * tk;
                float xa = h1[s0 * 52 + t], xb = h1[(s0 + 1) * 52 + t];
                cc[n][0] = fmaf(wi0, xa, bv0);
                cc[n][1] = fmaf(wi0, xb, bv0);
                cc[n][2] = fmaf(wi1, xa, bv1);
                cc[n][3] = fmaf(wi1, xb, bv1);
            }

            // recurrence: cc += Whh @ h  (3-term bf16, A resident)
            #pragma unroll
            for (int ks = 0; ks < 4; ks++) {
                #pragma unroll
                for (int n = 0; n < 8; n++) {
                    int wd = (n * 8 + grp) * 36 + ks * 8 + tk;
                    uint32_t bh0 = hth[wd], bh1 = hth[wd + 4];
                    uint32_t bl0 = htl[wd], bl1 = htl[wd + 4];
                    MMA(cc[n], &wa[(ks * 2 + 0) * 4], bh0, bh1);
                    MMA(cc[n], &wa[(ks * 2 + 0) * 4], bl0, bl1);
                    MMA(cc[n], &wa[(ks * 2 + 1) * 4], bh0, bh1);
                }
            }

            // scatter gates to gact[sample][gate]
            #pragma unroll
            for (int n = 0; n < 8; n++) {
                int s0 = n * 8 + 2 * tk, gcol = w * 16 + grp;
                ga[s0 * 260 + gcol]           = cc[n][0];
                ga[(s0 + 1) * 260 + gcol]     = cc[n][1];
                ga[s0 * 260 + gcol + 8]       = cc[n][2];
                ga[(s0 + 1) * 260 + gcol + 8] = cc[n][3];
            }
            __syncthreads();

            // state update: thread (j,q) -> samples s = q + 8*si
            #pragma unroll
            for (int si = 0; si < 8; si++) {
                const int s = q + si * 8;
                float gi = ga[s * 260 + j],       gf = ga[s * 260 + 64 + j];
                float gg = ga[s * 260 + 128 + j], go = ga[s * 260 + 192 + j];
                float c = fmaf(sig_fast(gf), c8[si], sig_fast(gi) * tanh_fast(gg));
                c8[si] = c;
                float h = sig_fast(go) * tanh_fast(c);
                g_seq1[((size_t)(blk * 64 + s) * T1 + t) * 128 + d * 64 + j] = h;
                __nv_bfloat16 hh = __float2bfloat16_rn(h);
                __nv_bfloat16 hl = __float2bfloat16_rn(h - __bfloat162float(hh));
                ((__nv_bfloat16*)hth)[s * 72 + j] = hh;
                ((__nv_bfloat16*)htl)[s * 72 + j] = hl;
            }
            __syncthreads();
        }
    }
}

// ===========================================================================
// k_proj v3: double-buffered x staging (unchanged from round 13)
// grid = (d, blk, half) = 512 CTAs x 25 m each
// ===========================================================================
#define PJ_W  0                         // 128KB weight frags
#define PJ_X  131072                    // 2 buffers x (hi 17408 + lo 17408)
#define PJ_SM (131072 + 69632)

__global__ __launch_bounds__(512, 1)
void k_proj(const float* __restrict__ b2_f, const float* __restrict__ b2_b)
{
    extern __shared__ char smc[];
    uint32_t* wsm = (uint32_t*)(smc + PJ_W);

    const int tid = threadIdx.x;
    const int w   = tid >> 5, lid = tid & 31;
    const int grp = lid >> 2, tk = lid & 3;
    const int bi  = blockIdx.x;
    const int d   = bi >> 8, blk = (bi >> 1) & 127, half = bi & 1;
    const int m0  = half * 25;

    const float* bg = d ? b2_b : b2_f;
    const float bv0 = __ldg(&bg[w * 16 + grp]);
    const float bv1 = __ldg(&bg[w * 16 + grp + 8]);

    {
        const uint32_t* src = g_wihf + d * 32768;
        for (int p = tid; p < 32768; p += 512) wsm[p] = __ldg(src + p);
    }
    const uint32_t* wp = wsm + w * 2048 + lid;

    const int srow = tid >> 3, f0 = (tid & 7) * 16;
    const int wbase = srow * 68 + (f0 >> 1);

    float4 xr[4];
    {
        const float4* p = (const float4*)(g_seq1 +
            ((size_t)(blk * 64 + srow) * T1 + m0) * 128 + f0);
        #pragma unroll
        for (int i = 0; i < 4; i++) xr[i] = __ldg(p + i);
    }
    __syncthreads();

    for (int mi = 0; mi < 25; mi++) {
        const int m = m0 + mi;
        uint32_t* xth = (uint32_t*)(smc + PJ_X + (mi & 1) * 34816);
        uint32_t* xtl = xth + 4352;

        #pragma unroll
        for (int i = 0; i < 4; i++) {
            uint32_t h0, l0, h1, l1;
            split_pair(xr[i].x, xr[i].y, h0, l0);
            split_pair(xr[i].z, xr[i].w, h1, l1);
            xth[wbase + i * 2] = h0; xth[wbase + i * 2 + 1] = h1;
            xtl[wbase + i * 2] = l0; xtl[wbase + i * 2 + 1] = l1;
        }
        __syncthreads();

        if (mi < 24) {
            const float4* p = (const float4*)(g_seq1 +
                ((size_t)(blk * 64 + srow) * T1 + (m + 1)) * 128 + f0);
            #pragma unroll
            for (int i = 0; i < 4; i++) xr[i] = __ldg(p + i);
        }

        float cc[8][4];
        #pragma unroll
        for (int n = 0; n < 8; n++) {
            cc[n][0] = bv0; cc[n][1] = bv0; cc[n][2] = bv1; cc[n][3] = bv1;
        }
        for (int ks = 0; ks < 8; ks++) {
            uint32_t ah[4], al[4];
            #pragma unroll
            for (int r = 0; r < 4; r++) {
                ah[r] = wp[ks * 256 + r * 32];
                al[r] = wp[ks * 256 + 128 + r * 32];
            }
            #pragma unroll
            for (int n = 0; n < 8; n++) {
                int wd = (n * 8 + grp) * 68 + ks * 8 + tk;
                uint32_t bh0 = xth[wd], bh1 = xth[wd + 4];
                uint32_t bl0 = xtl[wd], bl1 = xtl[wd + 4];
                MMA(cc[n], ah, bh0, bh1);
                MMA(cc[n], ah, bl0, bl1);
                MMA(cc[n], al, bh0, bh1);
            }
        }
        float* op = g_xg + ((((size_t)(d * 128 + blk) * 50 + m) * 16 + w) * 8) * 128 + lid * 4;
        #pragma unroll
        for (int n = 0; n < 8; n++) {
            float4 v;
            v.x = cc[n][0]; v.y = cc[n][1]; v.z = cc[n][2]; v.w = cc[n][3];
            *(float4*)(op + n * 128) = v;
        }
        __syncthreads();
    }
}

// ===========================================================================
// k_layer2: BiLSTM layer 2 recurrence (mma) + fc2 + tanh (unchanged round 13)
// ===========================================================================
#define HT_HI 0
#define HT_LO 9216
#define GACTO 18432
#define HBUFO 84992
#define OUTAO 102400
#define L2_SM 128000

__global__ __launch_bounds__(512, 1)
void k_layer2(const float* __restrict__ fc2_w, const float* __restrict__ fc2_b,
              float* __restrict__ out)
{
    extern __shared__ char smc[];
    uint32_t* hth = (uint32_t*)(smc + HT_HI);
    uint32_t* htl = (uint32_t*)(smc + HT_LO);
    float*    ga  = (float*)(smc + GACTO);
    float*    hbf = (float*)(smc + HBUFO);
    float*    oa  = (float*)(smc + OUTAO);

    const int tid = threadIdx.x;
    const int w   = tid >> 5, lid = tid & 31;
    const int grp = lid >> 2, tk = lid & 3;
    const int j = tid & 63, q = tid >> 6;
    const int blk = blockIdx.x;
    const float fc2bv = __ldg(fc2_b);

    for (int d = 0; d < 2; d++) {
        const float fwa = __ldg(&fc2_w[d * 64 + lid]);
        const float fwb = __ldg(&fc2_w[d * 64 + 32 + lid]);

        uint32_t wa[32];
        {
            const uint32_t* hp = g_whhf + (d * 16 + w) * 4 * 256 + lid;
            #pragma unroll
            for (int ks = 0; ks < 4; ks++)
                #pragma unroll
                for (int tm = 0; tm < 2; tm++)
                    #pragma unroll
                    for (int r = 0; r < 4; r++)
                        wa[(ks * 2 + tm) * 4 + r] = __ldg(hp + (ks * 2 + tm) * 128 + r * 32);
        }

        __syncthreads();
        for (int p = tid; p < 4608; p += 512) hth[p] = 0u;
        float c8[8];
        #pragma unroll
        for (int i = 0; i < 8; i++) c8[i] = 0.f;

        float xgv[32];
        {
            const int m0 = d ? 49 : 0;
            const float* xp = g_xg + ((((size_t)(d * 128 + blk) * 50 + m0) * 16 + w) * 8) * 128 + lid * 4;
            #pragma unroll
            for (int n = 0; n < 8; n++) {
                float4 v = __ldg((const float4*)(xp + n * 128));
                xgv[n * 4 + 0] = v.x; xgv[n * 4 + 1] = v.y;
                xgv[n * 4 + 2] = v.z; xgv[n * 4 + 3] = v.w;
            }
        }
        __syncthreads();

        for (int tt = 0; tt < T2; tt++) {
            const int t = d ? (T2 - 1 - tt) : tt;

            float cc[8][4];
            #pragma unroll
            for (int n = 0; n < 8; n++)
                #pragma unroll
                for (int r = 0; r < 4; r++) cc[n][r] = xgv[n * 4 + r];

            if (tt & 1) {
                const int m  = t >> 1;
                const int mn = d ? (m - 1) : (m + 1);
                if (mn >= 0 && mn < 50) {
                    const float* xp = g_xg + ((((size_t)(d * 128 + blk) * 50 + mn) * 16 + w) * 8) * 128 + lid * 4;
                    #pragma unroll
                    for (int n = 0; n < 8; n++) {
                        float4 v = __ldg((const float4*)(xp + n * 128));
                        xgv[n * 4 + 0] = v.x; xgv[n * 4 + 1] = v.y;
                        xgv[n * 4 + 2] = v.z; xgv[n * 4 + 3] = v.w;
                    }
                }
            }

            #pragma unroll
            for (int ks = 0; ks < 4; ks++) {
                #pragma unroll
                for (int n = 0; n < 8; n++) {
                    int wd = (n * 8 + grp) * 36 + ks * 8 + tk;
                    uint32_t bh0 = hth[wd], bh1 = hth[wd + 4];
                    uint32_t bl0 = htl[wd], bl1 = htl[wd + 4];
                    MMA(cc[n], &wa[(ks * 2 + 0) * 4], bh0, bh1);
                    MMA(cc[n], &wa[(ks * 2 + 0) * 4], bl0, bl1);
                    MMA(cc[n], &wa[(ks * 2 + 1) * 4], bh0, bh1);
                }
            }

            #pragma unroll
            for (int n = 0; n < 8; n++) {
                int s0 = n * 8 + 2 * tk, gcol = w * 16 + grp;
                ga[s0 * 260 + gcol]           = cc[n][0];
                ga[(s0 + 1) * 260 + gcol]     = cc[n][1];
                ga[s0 * 260 + gcol + 8]       = cc[n][2];
                ga[(s0 + 1) * 260 + gcol + 8] = cc[n][3];
            }
            __syncthreads();

            #pragma unroll
            for (int si = 0; si < 8; si++) {
                const int s = q + si * 8;
                float gi = ga[s * 260 + j],       gf = ga[s * 260 + 64 + j];
                float gg = ga[s * 260 + 128 + j], go = ga[s * 260 + 192 + j];
                float c = fmaf(sig_fast(gf), c8[si], sig_fast(gi) * tanh_fast(gg));
                c8[si] = c;
                float h = sig_fast(go) * tanh_fast(c);
                hbf[s * 68 + j] = h;
                __nv_bfloat16 hh = __float2bfloat16_rn(h);
                __nv_bfloat16 hl = __float2bfloat16_rn(h - __bfloat162float(hh));
                ((__nv_bfloat16*)hth)[s * 72 + j] = hh;
                ((__nv_bfloat16*)htl)[s * 72 + j] = hl;
            }
            __syncthreads();

            #pragma unroll
            for (int si2 = 0; si2 < 4; si2++) {
                const int s = w * 4 + si2;
                float pm = hbf[s * 68 + lid] * fwa + hbf[s * 68 + 32 + lid] * fwb;
                #pragma unroll
                for (int o = 16; o > 0; o >>= 1)
                    pm += __shfl_down_sync(0xffffffffu, pm, o);
                if (lid == 0) {
                    if (d == 0) oa[s * 100 + t] = pm;
                    else out[(size_t)(blk * 64 + s) * T2 + t] = ftanh_(oa[s * 100 + t] + pm + fc2bv);
                }
            }
        }
    }
}

// ---------------------------------------------------------------------------
extern "C" void kernel_launch(void* const* d_in, const int* in_sizes, int n_in,
                              void* d_out, int out_size)
{
    const float* x    = (const float*)d_in[0];
    const float* fc1w = (const float*)d_in[1];
    const float* fc1b = (const float*)d_in[2];
    const float* r1wf = (const float*)d_in[3];
    const float* r1hf = (const float*)d_in[4];
    const float* r1bf = (const float*)d_in[5];
    const float* r1wb = (const float*)d_in[6];
    const float* r1hb = (const float*)d_in[7];
    const float* r1bb = (const float*)d_in[8];
    const float* r2wf = (const float*)d_in[9];
    const float* r2hf = (const float*)d_in[10];
    const float* r2bf = (const float*)d_in[11];
    const float* r2wb = (const float*)d_in[12];
    const float* r2hb = (const float*)d_in[13];
    const float* r2bb = (const float*)d_in[14];
    const float* fc2w = (const float*)d_in[15];
    const float* fc2b = (const float*)d_in[16];
    float* out = (float*)d_out;

    cudaFuncSetAttribute(k_layer1, cudaFuncAttributeMaxDynamicSharedMemorySize, L1_SM);
    cudaFuncSetAttribute(k_proj,   cudaFuncAttributeMaxDynamicSharedMemorySize, PJ_SM);
    cudaFuncSetAttribute(k_layer2, cudaFuncAttributeMaxDynamicSharedMemorySize, L2_SM);

    k_prep<<<64, 256>>>(r2wf, r2wb, r2hf, r2hb, r1hf, r1hb);
    k_layer1<<<128, 512, L1_SM>>>(x, fc1w, fc1b, r1wf, r1bf, r1wb, r1bb);
    k_proj<<<512, 512, PJ_SM>>>(r2bf, r2bb);
    k_layer2<<<128, 512, L2_SM>>>(fc2w, fc2b, out);
}

// round 15
// speedup vs baseline: 1.6227x; 1.0347x over previous
#include <cuda_runtime.h>
#include <cuda_bf16.h>
#include <cstdint>

#define BT 8192
#define T1 50
#define T2 100

static __device__ float g_seq1[BT * T1 * 128];
static __device__ uint32_t g_wihf[2 * 16 * 8 * 2 * 4 * 32];   // layer2 Wih frags
static __device__ uint32_t g_whhf[2 * 16 * 4 * 2 * 4 * 32];   // layer2 Whh frags
static __device__ uint32_t g_whh1f[2 * 16 * 4 * 2 * 4 * 32];  // layer1 Whh frags
static __device__ float g_xg[2 * 128 * 50 * 16 * 1024];       // proj results (839MB)

__device__ __forceinline__ float ftanh_(float x) {
    float e = __expf(-2.f * fabsf(x));
    float r = __fdividef(1.f - e, 1.f + e);
    return copysignf(r, x);
}
__device__ __forceinline__ float tanh_fast(float x) {
    float y;
    asm("tanh.approx.f32 %0, %1;" : "=f"(y) : "f"(x));
    return y;
}
__device__ __forceinline__ float sig_fast(float x) {
    return fmaf(tanh_fast(0.5f * x), 0.5f, 0.5f);
}
__device__ __forceinline__ uint32_t pack_bf2(float v0, float v1) {
    __nv_bfloat162 t = __floats2bfloat162_rn(v0, v1);
    return *(uint32_t*)&t;
}
__device__ __forceinline__ void split_pair(float v0, float v1, uint32_t& hi, uint32_t& lo) {
    __nv_bfloat16 h0 = __float2bfloat16_rn(v0), h1 = __float2bfloat16_rn(v1);
    hi = ((uint32_t)*(uint16_t*)&h1 << 16) | *(uint16_t*)&h0;
    lo = pack_bf2(v0 - __bfloat162float(h0), v1 - __bfloat162float(h1));
}
#define MMA(c, a, b0, b1) \
    asm volatile("mma.sync.aligned.m16n8k16.row.col.f32.bf16.bf16.f32 " \
                 "{%0,%1,%2,%3},{%4,%5,%6,%7},{%8,%9},{%0,%1,%2,%3};" \
                 : "+f"((c)[0]), "+f"((c)[1]), "+f"((c)[2]), "+f"((c)[3]) \
                 : "r"((a)[0]), "r"((a)[1]), "r"((a)[2]), "r"((a)[3]), "r"(b0), "r"(b1))

// ===========================================================================
// k_prep (unchanged)
// ===========================================================================
__global__ void k_prep(const float* __restrict__ wf, const float* __restrict__ wb,
                       const float* __restrict__ hf, const float* __restrict__ hb,
                       const float* __restrict__ h1f, const float* __restrict__ h1b)
{
    const int gt = blockIdx.x * blockDim.x + threadIdx.x;
    const int nt = gridDim.x * blockDim.x;
    for (int e = gt; e < 2 * 16 * 8 * 4 * 32; e += nt) {
        int l = e & 31, r = (e >> 5) & 3, ks = (e >> 7) & 7, w = (e >> 10) & 15, d = e >> 14;
        const float* W = d ? wb : wf;
        int row = w * 16 + (l >> 2) + (r & 1) * 8;
        int col = ks * 16 + ((r >> 1) & 1) * 8 + (l & 3) * 2;
        uint32_t hi, lo;
        split_pair(W[row * 128 + col], W[row * 128 + col + 1], hi, lo);
        uint32_t base = (((d * 16 + w) * 8 + ks) * 2) * 128 + r * 32 + l;
        g_wihf[base] = hi; g_wihf[base + 128] = lo;
    }
    for (int e = gt; e < 2 * 16 * 4 * 4 * 32; e += nt) {
        int l = e & 31, r = (e >> 5) & 3, ks = (e >> 7) & 3, w = (e >> 9) & 15, d = e >> 13;
        int row = w * 16 + (l >> 2) + (r & 1) * 8;
        int col = ks * 16 + ((r >> 1) & 1) * 8 + (l & 3) * 2;
        uint32_t base = (((d * 16 + w) * 4 + ks) * 2) * 128 + r * 32 + l;
        uint32_t hi, lo;
        const float* W2 = d ? hb : hf;
        split_pair(W2[row * 64 + col], W2[row * 64 + col + 1], hi, lo);
        g_whhf[base] = hi; g_whhf[base + 128] = lo;
        const float* W1 = d ? h1b : h1f;
        split_pair(W1[row * 64 + col], W1[row * 64 + col + 1], hi, lo);
        g_whh1f[base] = hi; g_whh1f[base + 128] = lo;
    }
}

// ===========================================================================
// k_layer1 (mma, unchanged from round 14)
// ===========================================================================
#define L1_H1  0
#define L1_HTH 13312
#define L1_HTL 22528
#define L1_GA  31744
#define L1_SM  98304

__global__ __launch_bounds__(512, 1)
void k_layer1(const float* __restrict__ x,
              const float* __restrict__ fc1_w, const float* __restrict__ fc1_b,
              const float* __restrict__ wih_f, const float* __restrict__ b_f,
              const float* __restrict__ wih_b, const float* __restrict__ b_b)
{
    extern __shared__ char smc[];
    float*    h1  = (float*)(smc + L1_H1);
    uint32_t* hth = (uint32_t*)(smc + L1_HTH);
    uint32_t* htl = (uint32_t*)(smc + L1_HTL);
    float*    ga  = (float*)(smc + L1_GA);

    const int tid = threadIdx.x;
    const int w   = tid >> 5, lid = tid & 31;
    const int grp = lid >> 2, tk = lid & 3;
    const int j = tid & 63, q = tid >> 6;
    const int blk = blockIdx.x;

    for (int idx = tid; idx < 64 * T1; idx += 512) {
        int s = idx / T1, t = idx - s * T1;
        const float* xr = x + (size_t)(blk * 64 + s) * 20;
        const float* wr = fc1_w + t * 20;
        float acc = __ldg(&fc1_b[t]);
        #pragma unroll
        for (int i = 0; i < 20; i++) acc = fmaf(__ldg(xr + i), __ldg(wr + i), acc);
        h1[s * 52 + t] = acc;
    }

    for (int d = 0; d < 2; d++) {
        const float* bg  = d ? b_b : b_f;
        const float* wih = d ? wih_b : wih_f;
        const float bv0 = __ldg(&bg[w * 16 + grp]);
        const float bv1 = __ldg(&bg[w * 16 + grp + 8]);
        const float wi0 = __ldg(&wih[w * 16 + grp]);
        const float wi1 = __ldg(&wih[w * 16 + grp + 8]);

        uint32_t wa[32];
        {
            const uint32_t* hp = g_whh1f + (d * 16 + w) * 4 * 256 + lid;
            #pragma unroll
            for (int ks = 0; ks < 4; ks++)
                #pragma unroll
                for (int tm = 0; tm < 2; tm++)
                    #pragma unroll
                    for (int r = 0; r < 4; r++)
                        wa[(ks * 2 + tm) * 4 + r] = __ldg(hp + (ks * 2 + tm) * 128 + r * 32);
        }

        __syncthreads();
        for (int p = tid; p < 4608; p += 512) hth[p] = 0u;
        float c8[8];
        #pragma unroll
        for (int i = 0; i < 8; i++) c8[i] = 0.f;
        __syncthreads();

        for (int tt = 0; tt < T1; tt++) {
            const int t = d ? (T1 - 1 - tt) : tt;

            float cc[8][4];
            #pragma unroll
            for (int n = 0; n < 8; n++) {
                int s0 = n * 8 + 2 * tk;
                float xa = h1[s0 * 52 + t], xb = h1[(s0 + 1) * 52 + t];
                cc[n][0] = fmaf(wi0, xa, bv0);
                cc[n][1] = fmaf(wi0, xb, bv0);
                cc[n][2] = fmaf(wi1, xa, bv1);
                cc[n][3] = fmaf(wi1, xb, bv1);
            }

            #pragma unroll
            for (int ks = 0; ks < 4; ks++) {
                #pragma unroll
                for (int n = 0; n < 8; n++) {
                    int wd = (n * 8 + grp) * 36 + ks * 8 + tk;
                    uint32_t bh0 = hth[wd], bh1 = hth[wd + 4];
                    uint32_t bl0 = htl[wd], bl1 = htl[wd + 4];
                    MMA(cc[n], &wa[(ks * 2 + 0) * 4], bh0, bh1);
                    MMA(cc[n], &wa[(ks * 2 + 0) * 4], bl0, bl1);
                    MMA(cc[n], &wa[(ks * 2 + 1) * 4], bh0, bh1);
                }
            }

            #pragma unroll
            for (int n = 0; n < 8; n++) {
                int s0 = n * 8 + 2 * tk, gcol = w * 16 + grp;
                ga[s0 * 260 + gcol]           = cc[n][0];
                ga[(s0 + 1) * 260 + gcol]     = cc[n][1];
                ga[s0 * 260 + gcol + 8]       = cc[n][2];
                ga[(s0 + 1) * 260 + gcol + 8] = cc[n][3];
            }
            __syncthreads();

            #pragma unroll
            for (int si = 0; si < 8; si++) {
                const int s = q + si * 8;
                float gi = ga[s * 260 + j],       gf = ga[s * 260 + 64 + j];
                float gg = ga[s * 260 + 128 + j], go = ga[s * 260 + 192 + j];
                float c = fmaf(sig_fast(gf), c8[si], sig_fast(gi) * tanh_fast(gg));
                c8[si] = c;
                float h = sig_fast(go) * tanh_fast(c);
                g_seq1[((size_t)(blk * 64 + s) * T1 + t) * 128 + d * 64 + j] = h;
                __nv_bfloat16 hh = __float2bfloat16_rn(h);
                __nv_bfloat16 hl = __float2bfloat16_rn(h - __bfloat162float(hh));
                ((__nv_bfloat16*)hth)[s * 72 + j] = hh;
                ((__nv_bfloat16*)htl)[s * 72 + j] = hl;
            }
            __syncthreads();
        }
    }
}

// ===========================================================================
// k_proj v3 (unchanged from round 13/14)
// ===========================================================================
#define PJ_W  0
#define PJ_X  131072
#define PJ_SM (131072 + 69632)

__global__ __launch_bounds__(512, 1)
void k_proj(const float* __restrict__ b2_f, const float* __restrict__ b2_b)
{
    extern __shared__ char smc[];
    uint32_t* wsm = (uint32_t*)(smc + PJ_W);

    const int tid = threadIdx.x;
    const int w   = tid >> 5, lid = tid & 31;
    const int grp = lid >> 2, tk = lid & 3;
    const int bi  = blockIdx.x;
    const int d   = bi >> 8, blk = (bi >> 1) & 127, half = bi & 1;
    const int m0  = half * 25;

    const float* bg = d ? b2_b : b2_f;
    const float bv0 = __ldg(&bg[w * 16 + grp]);
    const float bv1 = __ldg(&bg[w * 16 + grp + 8]);

    {
        const uint32_t* src = g_wihf + d * 32768;
        for (int p = tid; p < 32768; p += 512) wsm[p] = __ldg(src + p);
    }
    const uint32_t* wp = wsm + w * 2048 + lid;

    const int srow = tid >> 3, f0 = (tid & 7) * 16;
    const int wbase = srow * 68 + (f0 >> 1);

    float4 xr[4];
    {
        const float4* p = (const float4*)(g_seq1 +
            ((size_t)(blk * 64 + srow) * T1 + m0) * 128 + f0);
        #pragma unroll
        for (int i = 0; i < 4; i++) xr[i] = __ldg(p + i);
    }
    __syncthreads();

    for (int mi = 0; mi < 25; mi++) {
        const int m = m0 + mi;
        uint32_t* xth = (uint32_t*)(smc + PJ_X + (mi & 1) * 34816);
        uint32_t* xtl = xth + 4352;

        #pragma unroll
        for (int i = 0; i < 4; i++) {
            uint32_t h0, l0, h1, l1;
            split_pair(xr[i].x, xr[i].y, h0, l0);
            split_pair(xr[i].z, xr[i].w, h1, l1);
            xth[wbase + i * 2] = h0; xth[wbase + i * 2 + 1] = h1;
            xtl[wbase + i * 2] = l0; xtl[wbase + i * 2 + 1] = l1;
        }
        __syncthreads();

        if (mi < 24) {
            const float4* p = (const float4*)(g_seq1 +
                ((size_t)(blk * 64 + srow) * T1 + (m + 1)) * 128 + f0);
            #pragma unroll
            for (int i = 0; i < 4; i++) xr[i] = __ldg(p + i);
        }

        float cc[8][4];
        #pragma unroll
        for (int n = 0; n < 8; n++) {
            cc[n][0] = bv0; cc[n][1] = bv0; cc[n][2] = bv1; cc[n][3] = bv1;
        }
        for (int ks = 0; ks < 8; ks++) {
            uint32_t ah[4], al[4];
            #pragma unroll
            for (int r = 0; r < 4; r++) {
                ah[r] = wp[ks * 256 + r * 32];
                al[r] = wp[ks * 256 + 128 + r * 32];
            }
            #pragma unroll
            for (int n = 0; n < 8; n++) {
                int wd = (n * 8 + grp) * 68 + ks * 8 + tk;
                uint32_t bh0 = xth[wd], bh1 = xth[wd + 4];
                uint32_t bl0 = xtl[wd], bl1 = xtl[wd + 4];
                MMA(cc[n], ah, bh0, bh1);
                MMA(cc[n], ah, bl0, bl1);
                MMA(cc[n], al, bh0, bh1);
            }
        }
        float* op = g_xg + ((((size_t)(d * 128 + blk) * 50 + m) * 16 + w) * 8) * 128 + lid * 4;
        #pragma unroll
        for (int n = 0; n < 8; n++) {
            float4 v;
            v.x = cc[n][0]; v.y = cc[n][1]; v.z = cc[n][2]; v.w = cc[n][3];
            *(float4*)(op + n * 128) = v;
        }
        __syncthreads();
    }
}

// ===========================================================================
// k_layer2 v2: half-split software pipeline.
// CTA = 64 samples = halves A (0-31) / B (32-63), independent recurrences.
// Per step: MMA-A | epi-B(t-1) || fc2-B + scatter-A || MMA-B | epi-A(t) ||
//           fc2-A + scatter-B.  ga/hbf single-buffered, barrier-alternated.
// ===========================================================================
#define L2_HTA 0            // A hi tile  1152 words
#define L2_HLA 4608         // A lo
#define L2_HTB 9216         // B hi
#define L2_HLB 13824        // B lo
#define L2_GA  18432        // 32*260*4 = 33280
#define L2_HBF 51712        // 32*68*4  = 8704
#define L2_OA  60416        // 64*100*4 = 25600
#define L2_SM  86016

__global__ __launch_bounds__(512, 1)
void k_layer2(const float* __restrict__ fc2_w, const float* __restrict__ fc2_b,
              float* __restrict__ out)
{
    extern __shared__ char smc[];
    uint32_t* hthA = (uint32_t*)(smc + L2_HTA);
    uint32_t* htlA = (uint32_t*)(smc + L2_HLA);
    uint32_t* hthB = (uint32_t*)(smc + L2_HTB);
    uint32_t* htlB = (uint32_t*)(smc + L2_HLB);
    float*    ga   = (float*)(smc + L2_GA);
    float*    hbf  = (float*)(smc + L2_HBF);
    float*    oa   = (float*)(smc + L2_OA);

    const int tid = threadIdx.x;
    const int w   = tid >> 5, lid = tid & 31;
    const int grp = lid >> 2, tk = lid & 3;
    const int j = tid & 63, q = tid >> 6;
    const int blk = blockIdx.x;
    const float fc2bv = __ldg(fc2_b);

    for (int d = 0; d < 2; d++) {
        const float fwa = __ldg(&fc2_w[d * 64 + lid]);
        const float fwb = __ldg(&fc2_w[d * 64 + 32 + lid]);

        // resident Whh A-fragments (shared by both halves)
        uint32_t wa[32];
        {
            const uint32_t* hp = g_whhf + (d * 16 + w) * 4 * 256 + lid;
            #pragma unroll
            for (int ks = 0; ks < 4; ks++)
                #pragma unroll
                for (int tm = 0; tm < 2; tm++)
                    #pragma unroll
                    for (int r = 0; r < 4; r++)
                        wa[(ks * 2 + tm) * 4 + r] = __ldg(hp + (ks * 2 + tm) * 128 + r * 32);
        }

        __syncthreads();
        for (int p = tid; p < 4608; p += 512) hthA[p] = 0u;   // zeros all 4 tiles
        float c8A[4] = {0.f, 0.f, 0.f, 0.f};
        float c8B[4] = {0.f, 0.f, 0.f, 0.f};

        // initial xg for both halves (pair m0)
        float xgA[16], xgB[16];
        {
            const int m0 = d ? 49 : 0;
            const float* xp = g_xg + ((((size_t)(d * 128 + blk) * 50 + m0) * 16 + w) * 8) * 128 + lid * 4;
            #pragma unroll
            for (int nl = 0; nl < 4; nl++) {
                float4 v = __ldg((const float4*)(xp + nl * 128));
                xgA[nl * 4 + 0] = v.x; xgA[nl * 4 + 1] = v.y;
                xgA[nl * 4 + 2] = v.z; xgA[nl * 4 + 3] = v.w;
                float4 u = __ldg((const float4*)(xp + (4 + nl) * 128));
                xgB[nl * 4 + 0] = u.x; xgB[nl * 4 + 1] = u.y;
                xgB[nl * 4 + 2] = u.z; xgB[nl * 4 + 3] = u.w;
            }
        }
        __syncthreads();

        float cc[4][4];
        for (int tt = 0; tt < T2; tt++) {
            const int t  = d ? (T2 - 1 - tt) : tt;
            const int tp = d ? (t + 1) : (t - 1);
            const bool pf = (tt & 1) && (tt < 99);
            const int mn = pf ? (d ? ((t >> 1) - 1) : ((t >> 1) + 1)) : 0;
            const float* xpn = g_xg + ((((size_t)(d * 128 + blk) * 50 + mn) * 16 + w) * 8) * 128 + lid * 4;

            // ---- Phase A: MMA half A (step tt) ----
            #pragma unroll
            for (int nl = 0; nl < 4; nl++)
                #pragma unroll
                for (int r = 0; r < 4; r++) cc[nl][r] = xgA[nl * 4 + r];
            if (pf) {
                #pragma unroll
                for (int nl = 0; nl < 4; nl++) {
                    float4 v = __ldg((const float4*)(xpn + nl * 128));
                    xgA[nl * 4 + 0] = v.x; xgA[nl * 4 + 1] = v.y;
                    xgA[nl * 4 + 2] = v.z; xgA[nl * 4 + 3] = v.w;
                }
            }
            #pragma unroll
            for (int ks = 0; ks < 4; ks++) {
                #pragma unroll
                for (int nl = 0; nl < 4; nl++) {
                    int wd = (nl * 8 + grp) * 36 + ks * 8 + tk;
                    uint32_t bh0 = hthA[wd], bh1 = hthA[wd + 4];
                    uint32_t bl0 = htlA[wd], bl1 = htlA[wd + 4];
                    MMA(cc[nl], &wa[(ks * 2 + 0) * 4], bh0, bh1);
                    MMA(cc[nl], &wa[(ks * 2 + 0) * 4], bl0, bl1);
                    MMA(cc[nl], &wa[(ks * 2 + 1) * 4], bh0, bh1);
                }
            }

            // ---- Phase B: epilogue half B (step tt-1) ----
            if (tt > 0) {
                #pragma unroll
                for (int si = 0; si < 4; si++) {
                    const int sl = q + si * 8;
                    float gi = ga[sl * 260 + j],       gf = ga[sl * 260 + 64 + j];
                    float gg = ga[sl * 260 + 128 + j], go = ga[sl * 260 + 192 + j];
                    float c = fmaf(sig_fast(gf), c8B[si], sig_fast(gi) * tanh_fast(gg));
                    c8B[si] = c;
                    float h = sig_fast(go) * tanh_fast(c);
                    hbf[sl * 68 + j] = h;
                    __nv_bfloat16 hh = __float2bfloat16_rn(h);
                    __nv_bfloat16 hl = __float2bfloat16_rn(h - __bfloat162float(hh));
                    ((__nv_bfloat16*)hthB)[sl * 72 + j] = hh;
                    ((__nv_bfloat16*)htlB)[sl * 72 + j] = hl;
                }
            }
            __syncthreads();   // bar1

            // ---- Phase C: fc2 half B (tt-1) + scatter A ----
            if (tt > 0) {
                #pragma unroll
                for (int si2 = 0; si2 < 2; si2++) {
                    const int sl = w * 2 + si2, s = 32 + sl;
                    float pm = hbf[sl * 68 + lid] * fwa + hbf[sl * 68 + 32 + lid] * fwb;
                    #pragma unroll
                    for (int o = 16; o > 0; o >>= 1)
                        pm += __shfl_down_sync(0xffffffffu, pm, o);
                    if (lid == 0) {
                        if (d == 0) oa[s * 100 + tp] = pm;
                        else out[(size_t)(blk * 64 + s) * T2 + tp] = ftanh_(oa[s * 100 + tp] + pm + fc2bv);
                    }
                }
            }
            #pragma unroll
            for (int nl = 0; nl < 4; nl++) {
                int sl0 = nl * 8 + 2 * tk, gcol = w * 16 + grp;
                ga[sl0 * 260 + gcol]           = cc[nl][0];
                ga[(sl0 + 1) * 260 + gcol]     = cc[nl][1];
                ga[sl0 * 260 + gcol + 8]       = cc[nl][2];
                ga[(sl0 + 1) * 260 + gcol + 8] = cc[nl][3];
            }
            __syncthreads();   // bar2

            // ---- Phase D: MMA half B (step tt) ----
            #pragma unroll
            for (int nl = 0; nl < 4; nl++)
                #pragma unroll
                for (int r = 0; r < 4; r++) cc[nl][r] = xgB[nl * 4 + r];
            if (pf) {
                #pragma unroll
                for (int nl = 0; nl < 4; nl++) {
                    float4 u = __ldg((const float4*)(xpn + (4 + nl) * 128));
                    xgB[nl * 4 + 0] = u.x; xgB[nl * 4 + 1] = u.y;
                    xgB[nl * 4 + 2] = u.z; xgB[nl * 4 + 3] = u.w;
                }
            }
            #pragma unroll
            for (int ks = 0; ks < 4; ks++) {
                #pragma unroll
                for (int nl = 0; nl < 4; nl++) {
                    int wd = (nl * 8 + grp) * 36 + ks * 8 + tk;
                    uint32_t bh0 = hthB[wd], bh1 = hthB[wd + 4];
                    uint32_t bl0 = htlB[wd], bl1 = htlB[wd + 4];
                    MMA(cc[nl], &wa[(ks * 2 + 0) * 4], bh0, bh1);
                    MMA(cc[nl], &wa[(ks * 2 + 0) * 4], bl0, bl1);
                    MMA(cc[nl], &wa[(ks * 2 + 1) * 4], bh0, bh1);
                }
            }

            // ---- Phase E: epilogue half A (step tt) ----
            #pragma unroll
            for (int si = 0; si < 4; si++) {
                const int sl = q + si * 8;
                float gi = ga[sl * 260 + j],       gf = ga[sl * 260 + 64 + j];
                float gg = ga[sl * 260 + 128 + j], go = ga[sl * 260 + 192 + j];
                float c = fmaf(sig_fast(gf), c8A[si], sig_fast(gi) * tanh_fast(gg));
                c8A[si] = c;
                float h = sig_fast(go) * tanh_fast(c);
                hbf[sl * 68 + j] = h;
                __nv_bfloat16 hh = __float2bfloat16_rn(h);
                __nv_bfloat16 hl = __float2bfloat16_rn(h - __bfloat162float(hh));
                ((__nv_bfloat16*)hthA)[sl * 72 + j] = hh;
                ((__nv_bfloat16*)htlA)[sl * 72 + j] = hl;
            }
            __syncthreads();   // bar3

            // ---- Phase F: fc2 half A (tt) + scatter B ----
            #pragma unroll
            for (int si2 = 0; si2 < 2; si2++) {
                const int sl = w * 2 + si2, s = sl;
                float pm = hbf[sl * 68 + lid] * fwa + hbf[sl * 68 + 32 + lid] * fwb;
                #pragma unroll
                for (int o = 16; o > 0; o >>= 1)
                    pm += __shfl_down_sync(0xffffffffu, pm, o);
                if (lid == 0) {
                    if (d == 0) oa[s * 100 + t] = pm;
                    else out[(size_t)(blk * 64 + s) * T2 + t] = ftanh_(oa[s * 100 + t] + pm + fc2bv);
                }
            }
            #pragma unroll
            for (int nl = 0; nl < 4; nl++) {
                int sl0 = nl * 8 + 2 * tk, gcol = w * 16 + grp;
                ga[sl0 * 260 + gcol]           = cc[nl][0];
                ga[(sl0 + 1) * 260 + gcol]     = cc[nl][1];
                ga[sl0 * 260 + gcol + 8]       = cc[nl][2];
                ga[(sl0 + 1) * 260 + gcol + 8] = cc[nl][3];
            }
            __syncthreads();   // bar4
        }

        // ---- drain: epilogue + fc2 for half B, last step (tt = 99) ----
        {
            const int tl = d ? 0 : (T2 - 1);
            #pragma unroll
            for (int si = 0; si < 4; si++) {
                const int sl = q + si * 8;
                float gi = ga[sl * 260 + j],       gf = ga[sl * 260 + 64 + j];
                float gg = ga[sl * 260 + 128 + j], go = ga[sl * 260 + 192 + j];
                float c = fmaf(sig_fast(gf), c8B[si], sig_fast(gi) * tanh_fast(gg));
                c8B[si] = c;
                float h = sig_fast(go) * tanh_fast(c);
                hbf[sl * 68 + j] = h;
            }
            __syncthreads();
            #pragma unroll
            for (int si2 = 0; si2 < 2; si2++) {
                const int sl = w * 2 + si2, s = 32 + sl;
                float pm = hbf[sl * 68 + lid] * fwa + hbf[sl * 68 + 32 + lid] * fwb;
                #pragma unroll
                for (int o = 16; o > 0; o >>= 1)
                    pm += __shfl_down_sync(0xffffffffu, pm, o);
                if (lid == 0) {
                    if (d == 0) oa[s * 100 + tl] = pm;
                    else out[(size_t)(blk * 64 + s) * T2 + tl] = ftanh_(oa[s * 100 + tl] + pm + fc2bv);
                }
            }
            __syncthreads();
        }
    }
}

// ---------------------------------------------------------------------------
extern "C" void kernel_launch(void* const* d_in, const int* in_sizes, int n_in,
                              void* d_out, int out_size)
{
    const float* x    = (const float*)d_in[0];
    const float* fc1w = (const float*)d_in[1];
    const float* fc1b = (const float*)d_in[2];
    const float* r1wf = (const float*)d_in[3];
    const float* r1hf = (const float*)d_in[4];
    const float* r1bf = (const float*)d_in[5];
    const float* r1wb = (const float*)d_in[6];
    const float* r1hb = (const float*)d_in[7];
    const float* r1bb = (const float*)d_in[8];
    const float* r2wf = (const float*)d_in[9];
    const float* r2hf = (const float*)d_in[10];
    const float* r2bf = (const float*)d_in[11];
    const float* r2wb = (const float*)d_in[12];
    const float* r2hb = (const float*)d_in[13];
    const float* r2bb = (const float*)d_in[14];
    const float* fc2w = (const float*)d_in[15];
    const float* fc2b = (const float*)d_in[16];
    float* out = (float*)d_out;

    cudaFuncSetAttribute(k_layer1, cudaFuncAttributeMaxDynamicSharedMemorySize, L1_SM);
    cudaFuncSetAttribute(k_proj,   cudaFuncAttributeMaxDynamicSharedMemorySize, PJ_SM);
    cudaFuncSetAttribute(k_layer2, cudaFuncAttributeMaxDynamicSharedMemorySize, L2_SM);

    k_prep<<<64, 256>>>(r2wf, r2wb, r2hf, r2hb, r1hf, r1hb);
    k_layer1<<<128, 512, L1_SM>>>(x, fc1w, fc1b, r1wf, r1bf, r1wb, r1bb);
    k_proj<<<512, 512, PJ_SM>>>(r2bf, r2bb);
    k_layer2<<<128, 512, L2_SM>>>(fc2w, fc2b, out);
}